// round 14
// baseline (speedup 1.0000x reference)
#include <cuda_runtime.h>
#include <cuda_fp16.h>
#include <cstdint>

#define BB 4
#define SS 2048
#define NHD 16
#define DH 64
#define HH 1024
#define MTOT (BB*SS)     // 8192
#define KP2 2048         // packed A-side K ([hi|lo])
#define WKP 1024         // packed B-side (hi only, reused)
#define KQ 128           // packed Q k-dim [hi|lo]
#define LOG2E 1.4426950408889634f

#define ASLAB ((size_t)MTOT*KP2)
#define WSLAB ((size_t)HH*WKP)

// ------------------------- scratch (device globals) -------------------------
__device__ __half g_Xp[3*ASLAB];                 // packed acts (q,k,v); ctx in slab0
__device__ __half g_Wt[4*WSLAB];                 // W^T hi (fp16)
__device__ __half g_Qp[(size_t)BB*NHD*SS*KQ];    // [qhi|qlo]
__device__ __half g_Kp[(size_t)BB*NHD*SS*DH];    // k hi only
__device__ __half g_Vt[(size_t)BB*NHD*DH*SS];    // v^T hi only

// ------------------------- helpers -------------------------
__device__ __forceinline__ uint32_t s2u(const void* p) {
    uint32_t a;
    asm("{ .reg .u64 t; cvta.to.shared.u64 t, %1; cvt.u32.u64 %0, t; }" : "=r"(a) : "l"(p));
    return a;
}
#define CP_ASYNC16(dst, src) \
    asm volatile("cp.async.cg.shared.global [%0], [%1], 16;" :: "r"(dst), "l"(src))
#define CP_COMMIT() asm volatile("cp.async.commit_group;" ::: "memory")
#define CP_WAIT(n)  asm volatile("cp.async.wait_group %0;" :: "n"(n) : "memory")

__device__ __forceinline__ void ldm_x4(uint32_t* r, uint32_t addr) {
    asm volatile("ldmatrix.sync.aligned.m8n8.x4.shared.b16 {%0,%1,%2,%3}, [%4];"
        : "=r"(r[0]), "=r"(r[1]), "=r"(r[2]), "=r"(r[3]) : "r"(addr));
}
__device__ __forceinline__ void mma16816(float* d, const uint32_t* a, const uint32_t* b) {
    asm volatile("mma.sync.aligned.m16n8k16.row.col.f32.f16.f16.f32 "
        "{%0,%1,%2,%3}, {%4,%5,%6,%7}, {%8,%9}, {%0,%1,%2,%3};"
        : "+f"(d[0]), "+f"(d[1]), "+f"(d[2]), "+f"(d[3])
        : "r"(a[0]), "r"(a[1]), "r"(a[2]), "r"(a[3]), "r"(b[0]), "r"(b[1]));
}
__device__ __forceinline__ uint32_t pkh2(float lo, float hi) {   // low half = lo
    uint32_t r;
    asm("cvt.rn.f16x2.f32 %0, %1, %2;" : "=r"(r) : "f"(hi), "f"(lo));
    return r;
}
__device__ __forceinline__ void unpkh2(uint32_t p, float& lo, float& hi) {
    __half2 h = *(__half2*)&p;
    lo = __low2float(h); hi = __high2float(h);
}
__device__ __forceinline__ float ex2f(float x) {
    float r;
    asm("ex2.approx.ftz.f32 %0, %1;" : "=f"(r) : "f"(x));
    return r;
}

// ------------------------- pack kernels -------------------------
__global__ __launch_bounds__(256) void pack_a_k(
    const float* __restrict__ q, const float* __restrict__ k,
    const float* __restrict__ v, __half* __restrict__ xpBase)
{
    int z = blockIdx.y;
    const float* x = (z == 0) ? q : (z == 1) ? k : v;
    __half* xp = xpBase + (size_t)z * ASLAB;
    int i = blockIdx.x * 256 + threadIdx.x;
    int row = i >> 8;
    int k4 = (i & 255) << 2;
    float4 f = *(const float4*)&x[((size_t)row << 10) + k4];
    uint32_t p01 = pkh2(f.x, f.y), p23 = pkh2(f.z, f.w);
    float h0, h1, h2, h3;
    unpkh2(p01, h0, h1); unpkh2(p23, h2, h3);
    uint32_t l01 = pkh2(f.x - h0, f.y - h1), l23 = pkh2(f.z - h2, f.w - h3);
    size_t base = (size_t)row * KP2 + k4;
    *(uint32_t*)&xp[base]          = p01;
    *(uint32_t*)&xp[base + 2]      = p23;
    *(uint32_t*)&xp[base + 1024]   = l01;
    *(uint32_t*)&xp[base + 1026]   = l23;
}

__global__ __launch_bounds__(256) void pack_wt_k(
    const float* __restrict__ wq, const float* __restrict__ wk,
    const float* __restrict__ wv, const float* __restrict__ wo,
    __half* __restrict__ wtBase)
{
    __shared__ float t[32][33];
    int z = blockIdx.z;
    const float* W = (z == 0) ? wq : (z == 1) ? wk : (z == 2) ? wv : wo;
    __half* Wt = wtBase + (size_t)z * WSLAB;
    int tx = threadIdx.x & 31, ty = threadIdx.x >> 5;
    int n0 = blockIdx.x * 32, k0 = blockIdx.y * 32;
    #pragma unroll
    for (int r = 0; r < 4; r++) {
        int k = k0 + ty + r * 8;
        t[ty + r * 8][tx] = W[(size_t)k * HH + n0 + tx];
    }
    __syncthreads();
    #pragma unroll
    for (int r = 0; r < 4; r++) {
        int n = n0 + ty + r * 8;
        int k = k0 + tx;
        Wt[(size_t)n * WKP + k] = __float2half(t[tx][ty + r * 8]);
    }
}

// ------------------------- universal GEMM (R13 verbatim) -------------------------
#define LDS2 72
#define BUFA (128*LDS2*2)    // 18432
#define BUFB (256*LDS2*2)    // 36864
#define GSTAGE (2*BUFA+BUFB) // 73728
#define STG_STR 258

__global__ __launch_bounds__(256) void gemm_u(
    const __half* __restrict__ Abase, const __half* __restrict__ Wbase,
    float* __restrict__ outf, __half* __restrict__ outq,
    __half* __restrict__ outk, __half* __restrict__ outvt,
    const float* __restrict__ b0, const float* __restrict__ b1,
    const float* __restrict__ b2, int fixedMode)
{
    extern __shared__ char smem[];
    const int tid = threadIdx.x, wid = tid >> 5, lane = tid & 31;
    const int m0 = blockIdx.y * 128, n0 = blockIdx.x * 256;
    const int z = blockIdx.z;
    const int epi = (fixedMode < 0) ? z : fixedMode;

    const uint32_t sb = s2u(smem);

    const __half* Ab = Abase + ((fixedMode < 0) ? (size_t)z * ASLAB : 0) + (size_t)m0 * KP2;
    const __half* Bb = Wbase + ((fixedMode < 0) ? (size_t)z * WSLAB : 0) + (size_t)n0 * WKP;
    const float* bias = (epi == 0) ? b0 : (epi == 1) ? b1 : (epi == 2) ? b2 : b0;
    const float scale = (epi == 0) ? (0.125f * LOG2E) : 1.0f;
    constexpr int nC = 16;

    auto loadChunk = [&](int c, int s) {
        const uint32_t uAhi = sb + s * GSTAGE;
        const uint32_t uAlo = uAhi + BUFA;
        const uint32_t uB   = uAhi + 2 * BUFA;
        const __half* ahp = Ab + c * 64;
        const __half* alp = Ab + 1024 + c * 64;
        const __half* bp  = Bb + c * 64;
        #pragma unroll
        for (int p = 0; p < 4; p++) {
            int idx = tid + p * 256;
            int r = idx >> 3, sg = idx & 7;
            CP_ASYNC16(uAhi + r * (LDS2 * 2) + sg * 16,
                       (const char*)(ahp + (size_t)r * KP2) + sg * 16);
        }
        #pragma unroll
        for (int p = 0; p < 4; p++) {
            int idx = tid + p * 256;
            int r = idx >> 3, sg = idx & 7;
            CP_ASYNC16(uAlo + r * (LDS2 * 2) + sg * 16,
                       (const char*)(alp + (size_t)r * KP2) + sg * 16);
        }
        #pragma unroll
        for (int p = 0; p < 8; p++) {
            int idx = tid + p * 256;
            int r = idx >> 3, sg = idx & 7;
            CP_ASYNC16(uB + r * (LDS2 * 2) + sg * 16,
                       (const char*)(bp + (size_t)r * WKP) + sg * 16);
        }
        CP_COMMIT();
    };

    float acc[4][8][4];
    #pragma unroll
    for (int i = 0; i < 4; i++)
        #pragma unroll
        for (int j = 0; j < 8; j++)
            #pragma unroll
            for (int q = 0; q < 4; q++) acc[i][j][q] = 0.f;

    const int wm = (wid & 1) * 64;
    const int wn = (wid >> 1) * 64;

    loadChunk(0, 0);
    for (int c = 0; c < nC; c++) {
        int buf = c & 1;
        if (c + 1 < nC) { loadChunk(c + 1, (c + 1) & 1); CP_WAIT(1); }
        else CP_WAIT(0);
        __syncthreads();
        const uint32_t uAhi = sb + buf * GSTAGE;
        const uint32_t uAlo = uAhi + BUFA;
        const uint32_t uB   = uAhi + 2 * BUFA;
        #pragma unroll
        for (int ks = 0; ks < 4; ks++) {
            uint32_t ah[4][4], al[4][4];
            #pragma unroll
            for (int im = 0; im < 4; im++) {
                uint32_t off = ((wm + im * 16 + (lane & 15)) * LDS2
                                + ks * 16 + (lane >> 4) * 8) * 2;
                ldm_x4(ah[im], uAhi + off);
                ldm_x4(al[im], uAlo + off);
            }
            uint32_t b[4][4];
            #pragma unroll
            for (int ig = 0; ig < 4; ig++) {
                uint32_t addr = uB +
                    ((wn + ig * 16 + (lane & 7) + ((lane >> 4) << 3)) * LDS2
                     + ks * 16 + (((lane >> 3) & 1) << 3)) * 2;
                ldm_x4(b[ig], addr);
            }
            #pragma unroll
            for (int im = 0; im < 4; im++)
                #pragma unroll
                for (int ig = 0; ig < 4; ig++) {
                    mma16816(acc[im][ig * 2],     ah[im], &b[ig][0]);
                    mma16816(acc[im][ig * 2 + 1], ah[im], &b[ig][2]);
                }
            #pragma unroll
            for (int im = 0; im < 4; im++)
                #pragma unroll
                for (int ig = 0; ig < 4; ig++) {
                    mma16816(acc[im][ig * 2],     al[im], &b[ig][0]);
                    mma16816(acc[im][ig * 2 + 1], al[im], &b[ig][2]);
                }
        }
        __syncthreads();
    }

    // ------------------- epilogues -------------------
    if (epi == 2) {
        float* stage = (float*)smem;
        #pragma unroll
        for (int im = 0; im < 4; im++)
            #pragma unroll
            for (int jn = 0; jn < 8; jn++)
                #pragma unroll
                for (int h2 = 0; h2 < 2; h2++)
                    #pragma unroll
                    for (int cc = 0; cc < 2; cc++) {
                        int ml = wm + im * 16 + (lane >> 2) + h2 * 8;
                        int nl = wn + jn * 8 + (lane & 3) * 2 + cc;
                        stage[ml * STG_STR + nl] = acc[im][jn][h2 * 2 + cc] + bias[n0 + nl];
                    }
        __syncthreads();
        {
            const int bI = m0 >> 11, sBase = m0 & (SS - 1);
            int gl = tid;
            int gn = n0 + gl;
            int h = gn >> 6, d = gn & 63;
            size_t base = ((size_t)((bI * NHD + h) * DH + d)) * SS;
            #pragma unroll 4
            for (int sl = 0; sl < 128; sl++)
                outvt[base + sBase + sl] = __float2half(stage[sl * STG_STR + gl]);
        }
    } else if (epi == 3) {
        #pragma unroll
        for (int im = 0; im < 4; im++)
            #pragma unroll
            for (int jn = 0; jn < 8; jn++)
                #pragma unroll
                for (int h2 = 0; h2 < 2; h2++) {
                    int m = m0 + wm + im * 16 + (lane >> 2) + h2 * 8;
                    int gn = n0 + wn + jn * 8 + (lane & 3) * 2;
                    float2 r2;
                    r2.x = acc[im][jn][h2 * 2]     + bias[gn];
                    r2.y = acc[im][jn][h2 * 2 + 1] + bias[gn + 1];
                    *(float2*)&outf[(size_t)m * HH + gn] = r2;
                }
    } else {
        #pragma unroll
        for (int im = 0; im < 4; im++)
            #pragma unroll
            for (int jn = 0; jn < 8; jn++)
                #pragma unroll
                for (int h2 = 0; h2 < 2; h2++) {
                    int m = m0 + wm + im * 16 + (lane >> 2) + h2 * 8;
                    int gn = n0 + wn + jn * 8 + (lane & 3) * 2;
                    float v0 = (acc[im][jn][h2 * 2]     + bias[gn])     * scale;
                    float v1 = (acc[im][jn][h2 * 2 + 1] + bias[gn + 1]) * scale;
                    int h = gn >> 6, d = gn & 63;
                    int bI = m >> 11, sI = m & (SS - 1);
                    uint32_t phi = pkh2(v0, v1);
                    if (epi == 0) {  // Q: [hi | lo]
                        float fh0, fh1; unpkh2(phi, fh0, fh1);
                        uint32_t plo = pkh2(v0 - fh0, v1 - fh1);
                        size_t base = ((size_t)(bI * NHD + h) * SS + sI) * KQ;
                        *(uint32_t*)&outq[base + d]      = phi;
                        *(uint32_t*)&outq[base + 64 + d] = plo;
                    } else {         // K: hi only
                        size_t base = ((size_t)(bI * NHD + h) * SS + sI) * DH;
                        *(uint32_t*)&outk[base + d] = phi;
                    }
                }
    }
}

// ------------------------- fused flash attention (fp16; PV single-chain) -------------------------
#define QSTR 136
#define KSTR2 72
#define KBUF2 (128*KSTR2*2)   // 18432
#define VSTR 136
#define VBUF2 (64*VSTR*2)     // 17408

__global__ __launch_bounds__(256, 1) void flash_k(
    const __half* __restrict__ Qp, const __half* __restrict__ Kp,
    const __half* __restrict__ Vt, __half* __restrict__ Ctx)
{
    extern __shared__ char smem[];
    const int tid = threadIdx.x, wid = tid >> 5, lane = tid & 31;
    const int qt = blockIdx.x, bh = blockIdx.y;
    const int b_ = bh >> 4, h_ = bh & 15;
    const uint32_t sb = s2u(smem);
    const uint32_t uKb[2] = { sb, sb + KBUF2 };
    const uint32_t uVb[2] = { sb + 2 * KBUF2, sb + 2 * KBUF2 + VBUF2 };

    const __half* Qb = Qp + ((size_t)bh * SS + qt * 128) * KQ;
    const __half* Kb = Kp + (size_t)bh * SS * DH;
    const __half* Vb = Vt + (size_t)bh * DH * SS;

    auto issueK = [&](int it) {
        const __half* kp2 = Kb + (size_t)(it * 128) * DH;
        uint32_t dst = uKb[it & 1];
        #pragma unroll
        for (int p = 0; p < 4; p++) {
            int idx = tid + p * 256;
            int r = idx >> 3, sg = idx & 7;
            CP_ASYNC16(dst + r * (KSTR2 * 2) + sg * 16,
                       (const char*)(kp2 + (size_t)r * DH) + sg * 16);
        }
        CP_COMMIT();
    };
    auto issueV = [&](int it) {
        uint32_t dst = uVb[it & 1];
        int kt = it * 128;
        #pragma unroll
        for (int p = 0; p < 4; p++) {
            int idx = tid + p * 256;
            int r = idx >> 4, sg = idx & 15;
            CP_ASYNC16(dst + r * (VSTR * 2) + sg * 16,
                       (const char*)(Vb + (size_t)r * SS + kt) + sg * 16);
        }
        CP_COMMIT();
    };

    // prologue: stage Q across both K buffers
    #pragma unroll
    for (int p = 0; p < 8; p++) {
        int idx = tid + p * 256;
        int r = idx >> 4, sg = idx & 15;
        CP_ASYNC16(sb + r * (QSTR * 2) + sg * 16,
                   (const char*)(Qb + (size_t)r * KQ) + sg * 16);
    }
    CP_COMMIT();
    CP_WAIT(0); __syncthreads();

    uint32_t qf[8][4];
    {
        int rbase = wid * 16 + (lane & 15);
        #pragma unroll
        for (int kc = 0; kc < 8; kc++)
            ldm_x4(qf[kc], sb + (rbase * QSTR + kc * 16 + (lane >> 4) * 8) * 2);
    }
    __syncthreads();

    issueK(0); issueV(0);

    float oacc[8][4];
    #pragma unroll
    for (int j = 0; j < 8; j++)
        #pragma unroll
        for (int q = 0; q < 4; q++) oacc[j][q] = 0.f;
    float M0 = -1e30f, M1 = -1e30f, L0 = 0.f, L1 = 0.f;

    for (int i = 0; i < 16; i++) {
        CP_WAIT(0);
        __syncthreads();
        if (i + 1 < 16) { issueK(i + 1); issueV(i + 1); }

        const uint32_t kbase = uKb[i & 1];
        const uint32_t vbase = uVb[i & 1];

        // S = Q K^T  (logical K=128: kc 0-3 = Qhi*Khi, kc 4-7 = Qlo*Khi)
        float sc[16][4];
        #pragma unroll
        for (int t = 0; t < 16; t++)
            #pragma unroll
            for (int q = 0; q < 4; q++) sc[t][q] = 0.f;
        #pragma unroll
        for (int kc = 0; kc < 8; kc++) {
            #pragma unroll
            for (int kg = 0; kg < 8; kg++) {
                uint32_t b[4];
                uint32_t addr = kbase + ((kg * 16 + (lane & 7) + ((lane >> 4) << 3)) * KSTR2
                                         + (kc & 3) * 16 + (((lane >> 3) & 1) << 3)) * 2;
                ldm_x4(b, addr);
                mma16816(sc[kg * 2],     qf[kc], b);
                mma16816(sc[kg * 2 + 1], qf[kc], b + 2);
            }
        }

        // online softmax (log2 domain; Q pre-scaled by log2e/8)
        float m0 = -1e30f, m1 = -1e30f;
        #pragma unroll
        for (int t = 0; t < 16; t++) {
            m0 = fmaxf(m0, fmaxf(sc[t][0], sc[t][1]));
            m1 = fmaxf(m1, fmaxf(sc[t][2], sc[t][3]));
        }
        #pragma unroll
        for (int off = 1; off <= 2; off <<= 1) {
            m0 = fmaxf(m0, __shfl_xor_sync(0xffffffffu, m0, off));
            m1 = fmaxf(m1, __shfl_xor_sync(0xffffffffu, m1, off));
        }
        float nM0 = fmaxf(M0, m0), nM1 = fmaxf(M1, m1);
        float a0 = ex2f(M0 - nM0), a1 = ex2f(M1 - nM1);
        M0 = nM0; M1 = nM1;
        float s0 = 0.f, s1 = 0.f;
        #pragma unroll
        for (int t = 0; t < 16; t++) {
            sc[t][0] = ex2f(sc[t][0] - M0); s0 += sc[t][0];
            sc[t][1] = ex2f(sc[t][1] - M0); s0 += sc[t][1];
            sc[t][2] = ex2f(sc[t][2] - M1); s1 += sc[t][2];
            sc[t][3] = ex2f(sc[t][3] - M1); s1 += sc[t][3];
        }
        #pragma unroll
        for (int off = 1; off <= 2; off <<= 1) {
            s0 += __shfl_xor_sync(0xffffffffu, s0, off);
            s1 += __shfl_xor_sync(0xffffffffu, s1, off);
        }
        L0 = L0 * a0 + s0; L1 = L1 * a1 + s1;
        #pragma unroll
        for (int j = 0; j < 8; j++) {
            oacc[j][0] *= a0; oacc[j][1] *= a0;
            oacc[j][2] *= a1; oacc[j][3] *= a1;
        }

        // PV: single chain (P rounded to fp16; error absorbed in budget)
        #pragma unroll
        for (int j = 0; j < 8; j++) {
            uint32_t ph[4];
            ph[0] = pkh2(sc[2*j][0],   sc[2*j][1]);
            ph[1] = pkh2(sc[2*j][2],   sc[2*j][3]);
            ph[2] = pkh2(sc[2*j+1][0], sc[2*j+1][1]);
            ph[3] = pkh2(sc[2*j+1][2], sc[2*j+1][3]);

            uint32_t koff = (j * 16 + (((lane >> 3) & 1) << 3)) * 2;
            uint32_t rsel = (lane & 7) + ((lane >> 4) << 3);
            #pragma unroll
            for (int dg = 0; dg < 4; dg++) {
                uint32_t row = dg * 16 + rsel;
                uint32_t bh4[4];
                ldm_x4(bh4, vbase + row * (VSTR * 2) + koff);
                mma16816(oacc[dg * 2],     ph, bh4);
                mma16816(oacc[dg * 2 + 1], ph, bh4 + 2);
            }
        }
    }

    // epilogue: normalize + packed ctx write [hi | lo]
    float i0 = 1.f / L0, i1 = 1.f / L1;
    int r = lane >> 2;
    int q0 = qt * 128 + wid * 16;
    size_t row0 = ((size_t)(b_ * SS + q0 + r)) * KP2;
    size_t row1 = ((size_t)(b_ * SS + q0 + r + 8)) * KP2;
    int cbase = h_ * DH + (lane & 3) * 2;
    #pragma unroll
    for (int t = 0; t < 8; t++) {
        int col = cbase + t * 8;
        float v0 = oacc[t][0] * i0, v1 = oacc[t][1] * i0;
        float w0 = oacc[t][2] * i1, w1 = oacc[t][3] * i1;
        uint32_t pv = pkh2(v0, v1);
        uint32_t pw = pkh2(w0, w1);
        float vh0, vh1, wh0, wh1;
        unpkh2(pv, vh0, vh1); unpkh2(pw, wh0, wh1);
        *(uint32_t*)&Ctx[row0 + col]        = pv;
        *(uint32_t*)&Ctx[row0 + 1024 + col] = pkh2(v0 - vh0, v1 - vh1);
        *(uint32_t*)&Ctx[row1 + col]        = pw;
        *(uint32_t*)&Ctx[row1 + 1024 + col] = pkh2(w0 - wh0, w1 - wh1);
    }
}

// ------------------------- launch -------------------------
extern "C" void kernel_launch(void* const* d_in, const int* in_sizes, int n_in,
                              void* d_out, int out_size)
{
    const float* key   = (const float*)d_in[0];
    const float* value = (const float*)d_in[1];
    const float* query = (const float*)d_in[2];
    const float* wq = (const float*)d_in[3];
    const float* bq = (const float*)d_in[4];
    const float* wk = (const float*)d_in[5];
    const float* bk = (const float*)d_in[6];
    const float* wv = (const float*)d_in[7];
    const float* bv = (const float*)d_in[8];
    const float* wo = (const float*)d_in[9];
    const float* bo = (const float*)d_in[10];
    float* out = (float*)d_out;

    __half *xp, *wt, *qp, *kp, *vt;
    cudaGetSymbolAddress((void**)&xp, g_Xp);
    cudaGetSymbolAddress((void**)&wt, g_Wt);
    cudaGetSymbolAddress((void**)&qp, g_Qp);
    cudaGetSymbolAddress((void**)&kp, g_Kp);
    cudaGetSymbolAddress((void**)&vt, g_Vt);

    constexpr int SMG  = 2 * GSTAGE > 128 * STG_STR * 4 ? 2 * GSTAGE : 128 * STG_STR * 4; // 147456
    constexpr int SMFL = 2 * KBUF2 + 2 * VBUF2;       // 71680
    cudaFuncSetAttribute(gemm_u,  cudaFuncAttributeMaxDynamicSharedMemorySize, SMG);
    cudaFuncSetAttribute(flash_k, cudaFuncAttributeMaxDynamicSharedMemorySize, SMFL);

    pack_wt_k<<<dim3(32, 32, 4), 256>>>(wq, wk, wv, wo, wt);
    pack_a_k<<<dim3(MTOT * HH / 1024, 3), 256>>>(query, key, value, xp);

    // merged QKV projections (z: 0=Q,1=K,2=Vt), CTA 128x256
    gemm_u<<<dim3(4, 64, 3), 256, SMG>>>(xp, wt, nullptr, qp, kp, vt,
                                         bq, bk, bv, -1);

    // fused attention -> packed ctx in Xp slab 0
    flash_k<<<dim3(16, 64), 256, SMFL>>>(qp, kp, vt, xp);

    // output projection
    gemm_u<<<dim3(4, 64, 1), 256, SMG>>>(xp, wt + 3 * WSLAB, out,
                                         nullptr, nullptr, nullptr,
                                         bo, bo, bo, 3);
}

// round 15
// speedup vs baseline: 1.4048x; 1.4048x over previous
#include <cuda_runtime.h>
#include <cuda_fp16.h>
#include <cstdint>

#define BB 4
#define SS 2048
#define NHD 16
#define DH 64
#define HH 1024
#define MTOT (BB*SS)     // 8192
#define KP2 2048         // packed A-side K ([hi|lo])
#define WKP 1024         // packed B-side (hi only, reused)
#define KQ 128           // packed Q k-dim [hi|lo]
#define LOG2E 1.4426950408889634f

#define ASLAB ((size_t)MTOT*KP2)
#define WSLAB ((size_t)HH*WKP)

// ------------------------- scratch (device globals) -------------------------
__device__ __half g_Xp[3*ASLAB];                 // packed acts (q,k,v); ctx in slab0
__device__ __half g_Wt[4*WSLAB];                 // W^T hi (fp16)
__device__ __half g_Qp[(size_t)BB*NHD*SS*KQ];    // [qhi|qlo]
__device__ __half g_Kp[(size_t)BB*NHD*SS*DH];    // k hi only
__device__ __half g_Vt[(size_t)BB*NHD*DH*SS];    // v^T hi only

// ------------------------- helpers -------------------------
__device__ __forceinline__ uint32_t s2u(const void* p) {
    uint32_t a;
    asm("{ .reg .u64 t; cvta.to.shared.u64 t, %1; cvt.u32.u64 %0, t; }" : "=r"(a) : "l"(p));
    return a;
}
#define CP_ASYNC16(dst, src) \
    asm volatile("cp.async.cg.shared.global [%0], [%1], 16;" :: "r"(dst), "l"(src))
#define CP_COMMIT() asm volatile("cp.async.commit_group;" ::: "memory")
#define CP_WAIT(n)  asm volatile("cp.async.wait_group %0;" :: "n"(n) : "memory")

__device__ __forceinline__ void ldm_x4(uint32_t* r, uint32_t addr) {
    asm volatile("ldmatrix.sync.aligned.m8n8.x4.shared.b16 {%0,%1,%2,%3}, [%4];"
        : "=r"(r[0]), "=r"(r[1]), "=r"(r[2]), "=r"(r[3]) : "r"(addr));
}
__device__ __forceinline__ void mma16816(float* d, const uint32_t* a, const uint32_t* b) {
    asm volatile("mma.sync.aligned.m16n8k16.row.col.f32.f16.f16.f32 "
        "{%0,%1,%2,%3}, {%4,%5,%6,%7}, {%8,%9}, {%0,%1,%2,%3};"
        : "+f"(d[0]), "+f"(d[1]), "+f"(d[2]), "+f"(d[3])
        : "r"(a[0]), "r"(a[1]), "r"(a[2]), "r"(a[3]), "r"(b[0]), "r"(b[1]));
}
__device__ __forceinline__ uint32_t pkh2(float lo, float hi) {   // low half = lo
    uint32_t r;
    asm("cvt.rn.f16x2.f32 %0, %1, %2;" : "=r"(r) : "f"(hi), "f"(lo));
    return r;
}
__device__ __forceinline__ void unpkh2(uint32_t p, float& lo, float& hi) {
    __half2 h = *(__half2*)&p;
    lo = __low2float(h); hi = __high2float(h);
}
__device__ __forceinline__ float ex2f(float x) {
    float r;
    asm("ex2.approx.ftz.f32 %0, %1;" : "=f"(r) : "f"(x));
    return r;
}

// ------------------------- pack kernels -------------------------
__global__ __launch_bounds__(256) void pack_a_k(
    const float* __restrict__ q, const float* __restrict__ k,
    const float* __restrict__ v, __half* __restrict__ xpBase)
{
    int z = blockIdx.y;
    const float* x = (z == 0) ? q : (z == 1) ? k : v;
    __half* xp = xpBase + (size_t)z * ASLAB;
    int i = blockIdx.x * 256 + threadIdx.x;
    int row = i >> 8;
    int k4 = (i & 255) << 2;
    float4 f = *(const float4*)&x[((size_t)row << 10) + k4];
    uint32_t p01 = pkh2(f.x, f.y), p23 = pkh2(f.z, f.w);
    float h0, h1, h2, h3;
    unpkh2(p01, h0, h1); unpkh2(p23, h2, h3);
    uint32_t l01 = pkh2(f.x - h0, f.y - h1), l23 = pkh2(f.z - h2, f.w - h3);
    size_t base = (size_t)row * KP2 + k4;
    *(uint32_t*)&xp[base]          = p01;
    *(uint32_t*)&xp[base + 2]      = p23;
    *(uint32_t*)&xp[base + 1024]   = l01;
    *(uint32_t*)&xp[base + 1026]   = l23;
}

__global__ __launch_bounds__(256) void pack_wt_k(
    const float* __restrict__ wq, const float* __restrict__ wk,
    const float* __restrict__ wv, const float* __restrict__ wo,
    __half* __restrict__ wtBase)
{
    __shared__ float t[32][33];
    int z = blockIdx.z;
    const float* W = (z == 0) ? wq : (z == 1) ? wk : (z == 2) ? wv : wo;
    __half* Wt = wtBase + (size_t)z * WSLAB;
    int tx = threadIdx.x & 31, ty = threadIdx.x >> 5;
    int n0 = blockIdx.x * 32, k0 = blockIdx.y * 32;
    #pragma unroll
    for (int r = 0; r < 4; r++) {
        int k = k0 + ty + r * 8;
        t[ty + r * 8][tx] = W[(size_t)k * HH + n0 + tx];
    }
    __syncthreads();
    #pragma unroll
    for (int r = 0; r < 4; r++) {
        int n = n0 + ty + r * 8;
        int k = k0 + tx;
        Wt[(size_t)n * WKP + k] = __float2half(t[tx][ty + r * 8]);
    }
}

// ------------------------- universal GEMM: CTA 128x256, warp 64x64 -------------------------
// merged chunk = {A-hi 64k, A-lo 64k, B 64k (loaded once)}; nC = 16
#define LDS2 72
#define BUFA (128*LDS2*2)    // 18432
#define BUFB (256*LDS2*2)    // 36864
#define GSTAGE (2*BUFA+BUFB) // 73728
#define STG_STR 258

__global__ __launch_bounds__(256) void gemm_u(
    const __half* __restrict__ Abase, const __half* __restrict__ Wbase,
    float* __restrict__ outf, __half* __restrict__ outq,
    __half* __restrict__ outk, __half* __restrict__ outvt,
    const float* __restrict__ b0, const float* __restrict__ b1,
    const float* __restrict__ b2, int fixedMode)
{
    extern __shared__ char smem[];
    const int tid = threadIdx.x, wid = tid >> 5, lane = tid & 31;
    const int m0 = blockIdx.y * 128, n0 = blockIdx.x * 256;
    const int z = blockIdx.z;
    const int epi = (fixedMode < 0) ? z : fixedMode;

    const uint32_t sb = s2u(smem);

    const __half* Ab = Abase + ((fixedMode < 0) ? (size_t)z * ASLAB : 0) + (size_t)m0 * KP2;
    const __half* Bb = Wbase + ((fixedMode < 0) ? (size_t)z * WSLAB : 0) + (size_t)n0 * WKP;
    const float* bias = (epi == 0) ? b0 : (epi == 1) ? b1 : (epi == 2) ? b2 : b0;
    const float scale = (epi == 0) ? (0.125f * LOG2E) : 1.0f;
    constexpr int nC = 16;   // merged chunks of 64 k (x2 A-halves)

    auto loadChunk = [&](int c, int s) {
        const uint32_t uAhi = sb + s * GSTAGE;
        const uint32_t uAlo = uAhi + BUFA;
        const uint32_t uB   = uAhi + 2 * BUFA;
        const __half* ahp = Ab + c * 64;
        const __half* alp = Ab + 1024 + c * 64;
        const __half* bp  = Bb + c * 64;
        #pragma unroll
        for (int p = 0; p < 4; p++) {
            int idx = tid + p * 256;
            int r = idx >> 3, sg = idx & 7;
            CP_ASYNC16(uAhi + r * (LDS2 * 2) + sg * 16,
                       (const char*)(ahp + (size_t)r * KP2) + sg * 16);
        }
        #pragma unroll
        for (int p = 0; p < 4; p++) {
            int idx = tid + p * 256;
            int r = idx >> 3, sg = idx & 7;
            CP_ASYNC16(uAlo + r * (LDS2 * 2) + sg * 16,
                       (const char*)(alp + (size_t)r * KP2) + sg * 16);
        }
        #pragma unroll
        for (int p = 0; p < 8; p++) {
            int idx = tid + p * 256;
            int r = idx >> 3, sg = idx & 7;
            CP_ASYNC16(uB + r * (LDS2 * 2) + sg * 16,
                       (const char*)(bp + (size_t)r * WKP) + sg * 16);
        }
        CP_COMMIT();
    };

    float acc[4][8][4];
    #pragma unroll
    for (int i = 0; i < 4; i++)
        #pragma unroll
        for (int j = 0; j < 8; j++)
            #pragma unroll
            for (int q = 0; q < 4; q++) acc[i][j][q] = 0.f;

    const int wm = (wid & 1) * 64;
    const int wn = (wid >> 1) * 64;

    loadChunk(0, 0);
    for (int c = 0; c < nC; c++) {
        int buf = c & 1;
        if (c + 1 < nC) { loadChunk(c + 1, (c + 1) & 1); CP_WAIT(1); }
        else CP_WAIT(0);
        __syncthreads();
        const uint32_t uAhi = sb + buf * GSTAGE;
        const uint32_t uAlo = uAhi + BUFA;
        const uint32_t uB   = uAhi + 2 * BUFA;
        #pragma unroll
        for (int ks = 0; ks < 4; ks++) {
            uint32_t ah[4][4], al[4][4];
            #pragma unroll
            for (int im = 0; im < 4; im++) {
                uint32_t off = ((wm + im * 16 + (lane & 15)) * LDS2
                                + ks * 16 + (lane >> 4) * 8) * 2;
                ldm_x4(ah[im], uAhi + off);
                ldm_x4(al[im], uAlo + off);
            }
            uint32_t b[4][4];
            #pragma unroll
            for (int ig = 0; ig < 4; ig++) {
                uint32_t addr = uB +
                    ((wn + ig * 16 + (lane & 7) + ((lane >> 4) << 3)) * LDS2
                     + ks * 16 + (((lane >> 3) & 1) << 3)) * 2;
                ldm_x4(b[ig], addr);
            }
            // hi block (32 MMAs), then lo block (32 MMAs): acc reuse distance = 32
            #pragma unroll
            for (int im = 0; im < 4; im++)
                #pragma unroll
                for (int ig = 0; ig < 4; ig++) {
                    mma16816(acc[im][ig * 2],     ah[im], &b[ig][0]);
                    mma16816(acc[im][ig * 2 + 1], ah[im], &b[ig][2]);
                }
            #pragma unroll
            for (int im = 0; im < 4; im++)
                #pragma unroll
                for (int ig = 0; ig < 4; ig++) {
                    mma16816(acc[im][ig * 2],     al[im], &b[ig][0]);
                    mma16816(acc[im][ig * 2 + 1], al[im], &b[ig][2]);
                }
        }
        __syncthreads();
    }

    // ------------------- epilogues -------------------
    if (epi == 2) {
        float* stage = (float*)smem;
        #pragma unroll
        for (int im = 0; im < 4; im++)
            #pragma unroll
            for (int jn = 0; jn < 8; jn++)
                #pragma unroll
                for (int h2 = 0; h2 < 2; h2++)
                    #pragma unroll
                    for (int cc = 0; cc < 2; cc++) {
                        int ml = wm + im * 16 + (lane >> 2) + h2 * 8;
                        int nl = wn + jn * 8 + (lane & 3) * 2 + cc;
                        stage[ml * STG_STR + nl] = acc[im][jn][h2 * 2 + cc] + bias[n0 + nl];
                    }
        __syncthreads();
        {
            const int bI = m0 >> 11, sBase = m0 & (SS - 1);
            int gl = tid;
            int gn = n0 + gl;
            int h = gn >> 6, d = gn & 63;
            size_t base = ((size_t)((bI * NHD + h) * DH + d)) * SS;
            #pragma unroll 4
            for (int sl = 0; sl < 128; sl++)
                outvt[base + sBase + sl] = __float2half(stage[sl * STG_STR + gl]);
        }
    } else if (epi == 3) {
        #pragma unroll
        for (int im = 0; im < 4; im++)
            #pragma unroll
            for (int jn = 0; jn < 8; jn++)
                #pragma unroll
                for (int h2 = 0; h2 < 2; h2++) {
                    int m = m0 + wm + im * 16 + (lane >> 2) + h2 * 8;
                    int gn = n0 + wn + jn * 8 + (lane & 3) * 2;
                    float2 r2;
                    r2.x = acc[im][jn][h2 * 2]     + bias[gn];
                    r2.y = acc[im][jn][h2 * 2 + 1] + bias[gn + 1];
                    *(float2*)&outf[(size_t)m * HH + gn] = r2;
                }
    } else {
        #pragma unroll
        for (int im = 0; im < 4; im++)
            #pragma unroll
            for (int jn = 0; jn < 8; jn++)
                #pragma unroll
                for (int h2 = 0; h2 < 2; h2++) {
                    int m = m0 + wm + im * 16 + (lane >> 2) + h2 * 8;
                    int gn = n0 + wn + jn * 8 + (lane & 3) * 2;
                    float v0 = (acc[im][jn][h2 * 2]     + bias[gn])     * scale;
                    float v1 = (acc[im][jn][h2 * 2 + 1] + bias[gn + 1]) * scale;
                    int h = gn >> 6, d = gn & 63;
                    int bI = m >> 11, sI = m & (SS - 1);
                    uint32_t phi = pkh2(v0, v1);
                    if (epi == 0) {  // Q: [hi | lo]
                        float fh0, fh1; unpkh2(phi, fh0, fh1);
                        uint32_t plo = pkh2(v0 - fh0, v1 - fh1);
                        size_t base = ((size_t)(bI * NHD + h) * SS + sI) * KQ;
                        *(uint32_t*)&outq[base + d]      = phi;
                        *(uint32_t*)&outq[base + 64 + d] = plo;
                    } else {         // K: hi only
                        size_t base = ((size_t)(bI * NHD + h) * SS + sI) * DH;
                        *(uint32_t*)&outk[base + d] = phi;
                    }
                }
    }
}

// ------------------------- fused flash attention (fp16, 2-term) -------------------------
#define QSTR 136
#define KSTR2 72
#define KBUF2 (128*KSTR2*2)   // 18432
#define VSTR 136
#define VBUF2 (64*VSTR*2)     // 17408

__global__ __launch_bounds__(256, 1) void flash_k(
    const __half* __restrict__ Qp, const __half* __restrict__ Kp,
    const __half* __restrict__ Vt, __half* __restrict__ Ctx)
{
    extern __shared__ char smem[];
    const int tid = threadIdx.x, wid = tid >> 5, lane = tid & 31;
    const int qt = blockIdx.x, bh = blockIdx.y;
    const int b_ = bh >> 4, h_ = bh & 15;
    const uint32_t sb = s2u(smem);
    const uint32_t uKb[2] = { sb, sb + KBUF2 };
    const uint32_t uVb[2] = { sb + 2 * KBUF2, sb + 2 * KBUF2 + VBUF2 };

    const __half* Qb = Qp + ((size_t)bh * SS + qt * 128) * KQ;
    const __half* Kb = Kp + (size_t)bh * SS * DH;
    const __half* Vb = Vt + (size_t)bh * DH * SS;

    auto issueK = [&](int it) {
        const __half* kp2 = Kb + (size_t)(it * 128) * DH;
        uint32_t dst = uKb[it & 1];
        #pragma unroll
        for (int p = 0; p < 4; p++) {
            int idx = tid + p * 256;
            int r = idx >> 3, sg = idx & 7;
            CP_ASYNC16(dst + r * (KSTR2 * 2) + sg * 16,
                       (const char*)(kp2 + (size_t)r * DH) + sg * 16);
        }
        CP_COMMIT();
    };
    auto issueV = [&](int it) {
        uint32_t dst = uVb[it & 1];
        int kt = it * 128;
        #pragma unroll
        for (int p = 0; p < 4; p++) {
            int idx = tid + p * 256;
            int r = idx >> 4, sg = idx & 15;
            CP_ASYNC16(dst + r * (VSTR * 2) + sg * 16,
                       (const char*)(Vb + (size_t)r * SS + kt) + sg * 16);
        }
        CP_COMMIT();
    };

    // prologue: stage Q across both K buffers
    #pragma unroll
    for (int p = 0; p < 8; p++) {
        int idx = tid + p * 256;
        int r = idx >> 4, sg = idx & 15;
        CP_ASYNC16(sb + r * (QSTR * 2) + sg * 16,
                   (const char*)(Qb + (size_t)r * KQ) + sg * 16);
    }
    CP_COMMIT();
    CP_WAIT(0); __syncthreads();

    uint32_t qf[8][4];
    {
        int rbase = wid * 16 + (lane & 15);
        #pragma unroll
        for (int kc = 0; kc < 8; kc++)
            ldm_x4(qf[kc], sb + (rbase * QSTR + kc * 16 + (lane >> 4) * 8) * 2);
    }
    __syncthreads();

    issueK(0); issueV(0);

    float oacc[8][4];
    #pragma unroll
    for (int j = 0; j < 8; j++)
        #pragma unroll
        for (int q = 0; q < 4; q++) oacc[j][q] = 0.f;
    float M0 = -1e30f, M1 = -1e30f, L0 = 0.f, L1 = 0.f;

    for (int i = 0; i < 16; i++) {
        CP_WAIT(0);
        __syncthreads();
        if (i + 1 < 16) { issueK(i + 1); issueV(i + 1); }

        const uint32_t kbase = uKb[i & 1];
        const uint32_t vbase = uVb[i & 1];

        // S = Q K^T  (logical K=128: kc 0-3 = Qhi*Khi, kc 4-7 = Qlo*Khi)
        float sc[16][4];
        #pragma unroll
        for (int t = 0; t < 16; t++)
            #pragma unroll
            for (int q = 0; q < 4; q++) sc[t][q] = 0.f;
        #pragma unroll
        for (int kc = 0; kc < 8; kc++) {
            #pragma unroll
            for (int kg = 0; kg < 8; kg++) {
                uint32_t b[4];
                uint32_t addr = kbase + ((kg * 16 + (lane & 7) + ((lane >> 4) << 3)) * KSTR2
                                         + (kc & 3) * 16 + (((lane >> 3) & 1) << 3)) * 2;
                ldm_x4(b, addr);
                mma16816(sc[kg * 2],     qf[kc], b);
                mma16816(sc[kg * 2 + 1], qf[kc], b + 2);
            }
        }

        // online softmax (log2 domain; Q pre-scaled by log2e/8)
        float m0 = -1e30f, m1 = -1e30f;
        #pragma unroll
        for (int t = 0; t < 16; t++) {
            m0 = fmaxf(m0, fmaxf(sc[t][0], sc[t][1]));
            m1 = fmaxf(m1, fmaxf(sc[t][2], sc[t][3]));
        }
        #pragma unroll
        for (int off = 1; off <= 2; off <<= 1) {
            m0 = fmaxf(m0, __shfl_xor_sync(0xffffffffu, m0, off));
            m1 = fmaxf(m1, __shfl_xor_sync(0xffffffffu, m1, off));
        }
        float nM0 = fmaxf(M0, m0), nM1 = fmaxf(M1, m1);
        float a0 = ex2f(M0 - nM0), a1 = ex2f(M1 - nM1);
        M0 = nM0; M1 = nM1;
        float s0 = 0.f, s1 = 0.f;
        #pragma unroll
        for (int t = 0; t < 16; t++) {
            sc[t][0] = ex2f(sc[t][0] - M0); s0 += sc[t][0];
            sc[t][1] = ex2f(sc[t][1] - M0); s0 += sc[t][1];
            sc[t][2] = ex2f(sc[t][2] - M1); s1 += sc[t][2];
            sc[t][3] = ex2f(sc[t][3] - M1); s1 += sc[t][3];
        }
        #pragma unroll
        for (int off = 1; off <= 2; off <<= 1) {
            s0 += __shfl_xor_sync(0xffffffffu, s0, off);
            s1 += __shfl_xor_sync(0xffffffffu, s1, off);
        }
        L0 = L0 * a0 + s0; L1 = L1 * a1 + s1;
        #pragma unroll
        for (int j = 0; j < 8; j++) {
            oacc[j][0] *= a0; oacc[j][1] *= a0;
            oacc[j][2] *= a1; oacc[j][3] *= a1;
        }

        // PV: 2 chains  ((Phi + Plo) * Vhi)
        #pragma unroll
        for (int j = 0; j < 8; j++) {
            uint32_t ph[4], pl[4];
            float c00 = sc[2*j][0],   c01 = sc[2*j][1];
            float c02 = sc[2*j][2],   c03 = sc[2*j][3];
            float c10 = sc[2*j+1][0], c11 = sc[2*j+1][1];
            float c12 = sc[2*j+1][2], c13 = sc[2*j+1][3];
            ph[0] = pkh2(c00, c01); ph[1] = pkh2(c02, c03);
            ph[2] = pkh2(c10, c11); ph[3] = pkh2(c12, c13);
            float h00, h01, h02, h03, h10, h11, h12, h13;
            unpkh2(ph[0], h00, h01); unpkh2(ph[1], h02, h03);
            unpkh2(ph[2], h10, h11); unpkh2(ph[3], h12, h13);
            pl[0] = pkh2(c00 - h00, c01 - h01); pl[1] = pkh2(c02 - h02, c03 - h03);
            pl[2] = pkh2(c10 - h10, c11 - h11); pl[3] = pkh2(c12 - h12, c13 - h13);

            uint32_t koff = (j * 16 + (((lane >> 3) & 1) << 3)) * 2;
            uint32_t rsel = (lane & 7) + ((lane >> 4) << 3);
            #pragma unroll
            for (int dg = 0; dg < 4; dg++) {
                uint32_t row = dg * 16 + rsel;
                uint32_t bh4[4];
                ldm_x4(bh4, vbase + row * (VSTR * 2) + koff);
                mma16816(oacc[dg * 2],     ph, bh4);
                mma16816(oacc[dg * 2 + 1], ph, bh4 + 2);
                mma16816(oacc[dg * 2],     pl, bh4);
                mma16816(oacc[dg * 2 + 1], pl, bh4 + 2);
            }
        }
    }

    // epilogue: normalize + packed ctx write [hi | lo]
    float i0 = 1.f / L0, i1 = 1.f / L1;
    int r = lane >> 2;
    int q0 = qt * 128 + wid * 16;
    size_t row0 = ((size_t)(b_ * SS + q0 + r)) * KP2;
    size_t row1 = ((size_t)(b_ * SS + q0 + r + 8)) * KP2;
    int cbase = h_ * DH + (lane & 3) * 2;
    #pragma unroll
    for (int t = 0; t < 8; t++) {
        int col = cbase + t * 8;
        float v0 = oacc[t][0] * i0, v1 = oacc[t][1] * i0;
        float w0 = oacc[t][2] * i1, w1 = oacc[t][3] * i1;
        uint32_t pv = pkh2(v0, v1);
        uint32_t pw = pkh2(w0, w1);
        float vh0, vh1, wh0, wh1;
        unpkh2(pv, vh0, vh1); unpkh2(pw, wh0, wh1);
        *(uint32_t*)&Ctx[row0 + col]        = pv;
        *(uint32_t*)&Ctx[row0 + 1024 + col] = pkh2(v0 - vh0, v1 - vh1);
        *(uint32_t*)&Ctx[row1 + col]        = pw;
        *(uint32_t*)&Ctx[row1 + 1024 + col] = pkh2(w0 - wh0, w1 - wh1);
    }
}

// ------------------------- launch -------------------------
extern "C" void kernel_launch(void* const* d_in, const int* in_sizes, int n_in,
                              void* d_out, int out_size)
{
    const float* key   = (const float*)d_in[0];
    const float* value = (const float*)d_in[1];
    const float* query = (const float*)d_in[2];
    const float* wq = (const float*)d_in[3];
    const float* bq = (const float*)d_in[4];
    const float* wk = (const float*)d_in[5];
    const float* bk = (const float*)d_in[6];
    const float* wv = (const float*)d_in[7];
    const float* bv = (const float*)d_in[8];
    const float* wo = (const float*)d_in[9];
    const float* bo = (const float*)d_in[10];
    float* out = (float*)d_out;

    __half *xp, *wt, *qp, *kp, *vt;
    cudaGetSymbolAddress((void**)&xp, g_Xp);
    cudaGetSymbolAddress((void**)&wt, g_Wt);
    cudaGetSymbolAddress((void**)&qp, g_Qp);
    cudaGetSymbolAddress((void**)&kp, g_Kp);
    cudaGetSymbolAddress((void**)&vt, g_Vt);

    constexpr int SMG  = 2 * GSTAGE > 128 * STG_STR * 4 ? 2 * GSTAGE : 128 * STG_STR * 4; // 147456
    constexpr int SMFL = 2 * KBUF2 + 2 * VBUF2;       // 71680
    cudaFuncSetAttribute(gemm_u,  cudaFuncAttributeMaxDynamicSharedMemorySize, SMG);
    cudaFuncSetAttribute(flash_k, cudaFuncAttributeMaxDynamicSharedMemorySize, SMFL);

    pack_wt_k<<<dim3(32, 32, 4), 256>>>(wq, wk, wv, wo, wt);
    pack_a_k<<<dim3(MTOT * HH / 1024, 3), 256>>>(query, key, value, xp);

    // merged QKV projections (z: 0=Q,1=K,2=Vt), CTA 128x256
    gemm_u<<<dim3(4, 64, 3), 256, SMG>>>(xp, wt, nullptr, qp, kp, vt,
                                         bq, bk, bv, -1);

    // fused attention -> packed ctx in Xp slab 0
    flash_k<<<dim3(16, 64), 256, SMFL>>>(qp, kp, vt, xp);

    // output projection
    gemm_u<<<dim3(4, 64, 1), 256, SMG>>>(xp, wt + 3 * WSLAB, out,
                                         nullptr, nullptr, nullptr,
                                         bo, bo, bo, 3);
}

// round 16
// speedup vs baseline: 1.4376x; 1.0234x over previous
#include <cuda_runtime.h>
#include <cuda_fp16.h>
#include <cstdint>

#define BB 4
#define SS 2048
#define NHD 16
#define DH 64
#define HH 1024
#define MTOT (BB*SS)     // 8192
#define KP2 2048         // packed A-side K ([hi|lo])
#define WKP 1024         // packed B-side (hi only, reused)
#define KQ 128           // packed Q k-dim [hi|lo]
#define LOG2E 1.4426950408889634f

#define ASLAB ((size_t)MTOT*KP2)
#define WSLAB ((size_t)HH*WKP)

// ------------------------- scratch (device globals) -------------------------
__device__ __half g_Xp[3*ASLAB];                 // packed acts (q,k,v); ctx in slab0
__device__ __half g_Wt[4*WSLAB];                 // W^T hi (fp16)
__device__ __half g_Qp[(size_t)BB*NHD*SS*KQ];    // [qhi|qlo]
__device__ __half g_Kp[(size_t)BB*NHD*SS*DH];    // k hi only
__device__ __half g_Vt[(size_t)BB*NHD*DH*SS];    // v^T hi only

// ------------------------- helpers -------------------------
__device__ __forceinline__ uint32_t s2u(const void* p) {
    uint32_t a;
    asm("{ .reg .u64 t; cvta.to.shared.u64 t, %1; cvt.u32.u64 %0, t; }" : "=r"(a) : "l"(p));
    return a;
}
#define CP_ASYNC16(dst, src) \
    asm volatile("cp.async.cg.shared.global [%0], [%1], 16;" :: "r"(dst), "l"(src))
#define CP_COMMIT() asm volatile("cp.async.commit_group;" ::: "memory")
#define CP_WAIT(n)  asm volatile("cp.async.wait_group %0;" :: "n"(n) : "memory")

__device__ __forceinline__ void ldm_x4(uint32_t* r, uint32_t addr) {
    asm volatile("ldmatrix.sync.aligned.m8n8.x4.shared.b16 {%0,%1,%2,%3}, [%4];"
        : "=r"(r[0]), "=r"(r[1]), "=r"(r[2]), "=r"(r[3]) : "r"(addr));
}
__device__ __forceinline__ void mma16816(float* d, const uint32_t* a, const uint32_t* b) {
    asm volatile("mma.sync.aligned.m16n8k16.row.col.f32.f16.f16.f32 "
        "{%0,%1,%2,%3}, {%4,%5,%6,%7}, {%8,%9}, {%0,%1,%2,%3};"
        : "+f"(d[0]), "+f"(d[1]), "+f"(d[2]), "+f"(d[3])
        : "r"(a[0]), "r"(a[1]), "r"(a[2]), "r"(a[3]), "r"(b[0]), "r"(b[1]));
}
__device__ __forceinline__ uint32_t pkh2(float lo, float hi) {   // low half = lo
    uint32_t r;
    asm("cvt.rn.f16x2.f32 %0, %1, %2;" : "=r"(r) : "f"(hi), "f"(lo));
    return r;
}
__device__ __forceinline__ void unpkh2(uint32_t p, float& lo, float& hi) {
    __half2 h = *(__half2*)&p;
    lo = __low2float(h); hi = __high2float(h);
}
__device__ __forceinline__ float ex2f(float x) {
    float r;
    asm("ex2.approx.ftz.f32 %0, %1;" : "=f"(r) : "f"(x));
    return r;
}

// ------------------------- pack kernels (R13 verbatim) -------------------------
__global__ __launch_bounds__(256) void pack_a_k(
    const float* __restrict__ q, const float* __restrict__ k,
    const float* __restrict__ v, __half* __restrict__ xpBase)
{
    int z = blockIdx.y;
    const float* x = (z == 0) ? q : (z == 1) ? k : v;
    __half* xp = xpBase + (size_t)z * ASLAB;
    int i = blockIdx.x * 256 + threadIdx.x;
    int row = i >> 8;
    int k4 = (i & 255) << 2;
    float4 f = *(const float4*)&x[((size_t)row << 10) + k4];
    uint32_t p01 = pkh2(f.x, f.y), p23 = pkh2(f.z, f.w);
    float h0, h1, h2, h3;
    unpkh2(p01, h0, h1); unpkh2(p23, h2, h3);
    uint32_t l01 = pkh2(f.x - h0, f.y - h1), l23 = pkh2(f.z - h2, f.w - h3);
    size_t base = (size_t)row * KP2 + k4;
    *(uint32_t*)&xp[base]          = p01;
    *(uint32_t*)&xp[base + 2]      = p23;
    *(uint32_t*)&xp[base + 1024]   = l01;
    *(uint32_t*)&xp[base + 1026]   = l23;
}

__global__ __launch_bounds__(256) void pack_wt_k(
    const float* __restrict__ wq, const float* __restrict__ wk,
    const float* __restrict__ wv, const float* __restrict__ wo,
    __half* __restrict__ wtBase)
{
    __shared__ float t[32][33];
    int z = blockIdx.z;
    const float* W = (z == 0) ? wq : (z == 1) ? wk : (z == 2) ? wv : wo;
    __half* Wt = wtBase + (size_t)z * WSLAB;
    int tx = threadIdx.x & 31, ty = threadIdx.x >> 5;
    int n0 = blockIdx.x * 32, k0 = blockIdx.y * 32;
    #pragma unroll
    for (int r = 0; r < 4; r++) {
        int k = k0 + ty + r * 8;
        t[ty + r * 8][tx] = W[(size_t)k * HH + n0 + tx];
    }
    __syncthreads();
    #pragma unroll
    for (int r = 0; r < 4; r++) {
        int n = n0 + ty + r * 8;
        int k = k0 + tx;
        Wt[(size_t)n * WKP + k] = __float2half(t[tx][ty + r * 8]);
    }
}

// ------------------------- universal GEMM (R13 verbatim) -------------------------
#define LDS2 72
#define BUFA (128*LDS2*2)    // 18432
#define BUFB (256*LDS2*2)    // 36864
#define GSTAGE (2*BUFA+BUFB) // 73728
#define STG_STR 258

__global__ __launch_bounds__(256) void gemm_u(
    const __half* __restrict__ Abase, const __half* __restrict__ Wbase,
    float* __restrict__ outf, __half* __restrict__ outq,
    __half* __restrict__ outk, __half* __restrict__ outvt,
    const float* __restrict__ b0, const float* __restrict__ b1,
    const float* __restrict__ b2, int fixedMode)
{
    extern __shared__ char smem[];
    const int tid = threadIdx.x, wid = tid >> 5, lane = tid & 31;
    const int m0 = blockIdx.y * 128, n0 = blockIdx.x * 256;
    const int z = blockIdx.z;
    const int epi = (fixedMode < 0) ? z : fixedMode;

    const uint32_t sb = s2u(smem);

    const __half* Ab = Abase + ((fixedMode < 0) ? (size_t)z * ASLAB : 0) + (size_t)m0 * KP2;
    const __half* Bb = Wbase + ((fixedMode < 0) ? (size_t)z * WSLAB : 0) + (size_t)n0 * WKP;
    const float* bias = (epi == 0) ? b0 : (epi == 1) ? b1 : (epi == 2) ? b2 : b0;
    const float scale = (epi == 0) ? (0.125f * LOG2E) : 1.0f;
    constexpr int nC = 16;

    auto loadChunk = [&](int c, int s) {
        const uint32_t uAhi = sb + s * GSTAGE;
        const uint32_t uAlo = uAhi + BUFA;
        const uint32_t uB   = uAhi + 2 * BUFA;
        const __half* ahp = Ab + c * 64;
        const __half* alp = Ab + 1024 + c * 64;
        const __half* bp  = Bb + c * 64;
        #pragma unroll
        for (int p = 0; p < 4; p++) {
            int idx = tid + p * 256;
            int r = idx >> 3, sg = idx & 7;
            CP_ASYNC16(uAhi + r * (LDS2 * 2) + sg * 16,
                       (const char*)(ahp + (size_t)r * KP2) + sg * 16);
        }
        #pragma unroll
        for (int p = 0; p < 4; p++) {
            int idx = tid + p * 256;
            int r = idx >> 3, sg = idx & 7;
            CP_ASYNC16(uAlo + r * (LDS2 * 2) + sg * 16,
                       (const char*)(alp + (size_t)r * KP2) + sg * 16);
        }
        #pragma unroll
        for (int p = 0; p < 8; p++) {
            int idx = tid + p * 256;
            int r = idx >> 3, sg = idx & 7;
            CP_ASYNC16(uB + r * (LDS2 * 2) + sg * 16,
                       (const char*)(bp + (size_t)r * WKP) + sg * 16);
        }
        CP_COMMIT();
    };

    float acc[4][8][4];
    #pragma unroll
    for (int i = 0; i < 4; i++)
        #pragma unroll
        for (int j = 0; j < 8; j++)
            #pragma unroll
            for (int q = 0; q < 4; q++) acc[i][j][q] = 0.f;

    const int wm = (wid & 1) * 64;
    const int wn = (wid >> 1) * 64;

    loadChunk(0, 0);
    for (int c = 0; c < nC; c++) {
        int buf = c & 1;
        if (c + 1 < nC) { loadChunk(c + 1, (c + 1) & 1); CP_WAIT(1); }
        else CP_WAIT(0);
        __syncthreads();
        const uint32_t uAhi = sb + buf * GSTAGE;
        const uint32_t uAlo = uAhi + BUFA;
        const uint32_t uB   = uAhi + 2 * BUFA;
        #pragma unroll
        for (int ks = 0; ks < 4; ks++) {
            uint32_t ah[4][4], al[4][4];
            #pragma unroll
            for (int im = 0; im < 4; im++) {
                uint32_t off = ((wm + im * 16 + (lane & 15)) * LDS2
                                + ks * 16 + (lane >> 4) * 8) * 2;
                ldm_x4(ah[im], uAhi + off);
                ldm_x4(al[im], uAlo + off);
            }
            uint32_t b[4][4];
            #pragma unroll
            for (int ig = 0; ig < 4; ig++) {
                uint32_t addr = uB +
                    ((wn + ig * 16 + (lane & 7) + ((lane >> 4) << 3)) * LDS2
                     + ks * 16 + (((lane >> 3) & 1) << 3)) * 2;
                ldm_x4(b[ig], addr);
            }
            #pragma unroll
            for (int im = 0; im < 4; im++)
                #pragma unroll
                for (int ig = 0; ig < 4; ig++) {
                    mma16816(acc[im][ig * 2],     ah[im], &b[ig][0]);
                    mma16816(acc[im][ig * 2 + 1], ah[im], &b[ig][2]);
                }
            #pragma unroll
            for (int im = 0; im < 4; im++)
                #pragma unroll
                for (int ig = 0; ig < 4; ig++) {
                    mma16816(acc[im][ig * 2],     al[im], &b[ig][0]);
                    mma16816(acc[im][ig * 2 + 1], al[im], &b[ig][2]);
                }
        }
        __syncthreads();
    }

    // ------------------- epilogues -------------------
    if (epi == 2) {
        float* stage = (float*)smem;
        #pragma unroll
        for (int im = 0; im < 4; im++)
            #pragma unroll
            for (int jn = 0; jn < 8; jn++)
                #pragma unroll
                for (int h2 = 0; h2 < 2; h2++)
                    #pragma unroll
                    for (int cc = 0; cc < 2; cc++) {
                        int ml = wm + im * 16 + (lane >> 2) + h2 * 8;
                        int nl = wn + jn * 8 + (lane & 3) * 2 + cc;
                        stage[ml * STG_STR + nl] = acc[im][jn][h2 * 2 + cc] + bias[n0 + nl];
                    }
        __syncthreads();
        {
            const int bI = m0 >> 11, sBase = m0 & (SS - 1);
            int gl = tid;
            int gn = n0 + gl;
            int h = gn >> 6, d = gn & 63;
            size_t base = ((size_t)((bI * NHD + h) * DH + d)) * SS;
            #pragma unroll 4
            for (int sl = 0; sl < 128; sl++)
                outvt[base + sBase + sl] = __float2half(stage[sl * STG_STR + gl]);
        }
    } else if (epi == 3) {
        #pragma unroll
        for (int im = 0; im < 4; im++)
            #pragma unroll
            for (int jn = 0; jn < 8; jn++)
                #pragma unroll
                for (int h2 = 0; h2 < 2; h2++) {
                    int m = m0 + wm + im * 16 + (lane >> 2) + h2 * 8;
                    int gn = n0 + wn + jn * 8 + (lane & 3) * 2;
                    float2 r2;
                    r2.x = acc[im][jn][h2 * 2]     + bias[gn];
                    r2.y = acc[im][jn][h2 * 2 + 1] + bias[gn + 1];
                    *(float2*)&outf[(size_t)m * HH + gn] = r2;
                }
    } else {
        #pragma unroll
        for (int im = 0; im < 4; im++)
            #pragma unroll
            for (int jn = 0; jn < 8; jn++)
                #pragma unroll
                for (int h2 = 0; h2 < 2; h2++) {
                    int m = m0 + wm + im * 16 + (lane >> 2) + h2 * 8;
                    int gn = n0 + wn + jn * 8 + (lane & 3) * 2;
                    float v0 = (acc[im][jn][h2 * 2]     + bias[gn])     * scale;
                    float v1 = (acc[im][jn][h2 * 2 + 1] + bias[gn + 1]) * scale;
                    int h = gn >> 6, d = gn & 63;
                    int bI = m >> 11, sI = m & (SS - 1);
                    uint32_t phi = pkh2(v0, v1);
                    if (epi == 0) {  // Q: [hi | lo]
                        float fh0, fh1; unpkh2(phi, fh0, fh1);
                        uint32_t plo = pkh2(v0 - fh0, v1 - fh1);
                        size_t base = ((size_t)(bI * NHD + h) * SS + sI) * KQ;
                        *(uint32_t*)&outq[base + d]      = phi;
                        *(uint32_t*)&outq[base + 64 + d] = plo;
                    } else {         // K: hi only
                        size_t base = ((size_t)(bI * NHD + h) * SS + sI) * DH;
                        *(uint32_t*)&outk[base + d] = phi;
                    }
                }
    }
}

// ------------------------- fused flash attention: 128 threads, 64 q-rows, 2 CTAs/SM -------------------------
#define QSTR 136
#define KSTR2 72
#define KBUF2 (128*KSTR2*2)   // 18432
#define VSTR 136
#define VBUF2 (64*VSTR*2)     // 17408

__global__ __launch_bounds__(128, 2) void flash_k(
    const __half* __restrict__ Qp, const __half* __restrict__ Kp,
    const __half* __restrict__ Vt, __half* __restrict__ Ctx)
{
    extern __shared__ char smem[];
    const int tid = threadIdx.x, wid = tid >> 5, lane = tid & 31;
    const int qt = blockIdx.x, bh = blockIdx.y;
    const int b_ = bh >> 4, h_ = bh & 15;
    const uint32_t sb = s2u(smem);
    const uint32_t uKb[2] = { sb, sb + KBUF2 };
    const uint32_t uVb[2] = { sb + 2 * KBUF2, sb + 2 * KBUF2 + VBUF2 };

    const __half* Qb = Qp + ((size_t)bh * SS + qt * 64) * KQ;
    const __half* Kb = Kp + (size_t)bh * SS * DH;
    const __half* Vb = Vt + (size_t)bh * DH * SS;

    auto issueK = [&](int it) {
        const __half* kp2 = Kb + (size_t)(it * 128) * DH;
        uint32_t dst = uKb[it & 1];
        #pragma unroll
        for (int p = 0; p < 8; p++) {
            int idx = tid + p * 128;
            int r = idx >> 3, sg = idx & 7;
            CP_ASYNC16(dst + r * (KSTR2 * 2) + sg * 16,
                       (const char*)(kp2 + (size_t)r * DH) + sg * 16);
        }
        CP_COMMIT();
    };
    auto issueV = [&](int it) {
        uint32_t dst = uVb[it & 1];
        int kt = it * 128;
        #pragma unroll
        for (int p = 0; p < 8; p++) {
            int idx = tid + p * 128;
            int r = idx >> 4, sg = idx & 15;
            CP_ASYNC16(dst + r * (VSTR * 2) + sg * 16,
                       (const char*)(Vb + (size_t)r * SS + kt) + sg * 16);
        }
        CP_COMMIT();
    };

    // prologue: stage Q (64 rows x 128 halfs) into K-buffer region
    #pragma unroll
    for (int p = 0; p < 8; p++) {
        int idx = tid + p * 128;
        int r = idx >> 4, sg = idx & 15;
        CP_ASYNC16(sb + r * (QSTR * 2) + sg * 16,
                   (const char*)(Qb + (size_t)r * KQ) + sg * 16);
    }
    CP_COMMIT();
    CP_WAIT(0); __syncthreads();

    uint32_t qf[8][4];
    {
        int rbase = wid * 16 + (lane & 15);
        #pragma unroll
        for (int kc = 0; kc < 8; kc++)
            ldm_x4(qf[kc], sb + (rbase * QSTR + kc * 16 + (lane >> 4) * 8) * 2);
    }
    __syncthreads();

    issueK(0); issueV(0);

    float oacc[8][4];
    #pragma unroll
    for (int j = 0; j < 8; j++)
        #pragma unroll
        for (int q = 0; q < 4; q++) oacc[j][q] = 0.f;
    float M0 = -1e30f, M1 = -1e30f, L0 = 0.f, L1 = 0.f;

    for (int i = 0; i < 16; i++) {
        CP_WAIT(0);
        __syncthreads();
        if (i + 1 < 16) { issueK(i + 1); issueV(i + 1); }

        const uint32_t kbase = uKb[i & 1];
        const uint32_t vbase = uVb[i & 1];

        // S = Q K^T  (logical K=128: kc 0-3 = Qhi*Khi, kc 4-7 = Qlo*Khi)
        float sc[16][4];
        #pragma unroll
        for (int t = 0; t < 16; t++)
            #pragma unroll
            for (int q = 0; q < 4; q++) sc[t][q] = 0.f;
        #pragma unroll
        for (int kc = 0; kc < 8; kc++) {
            #pragma unroll
            for (int kg = 0; kg < 8; kg++) {
                uint32_t b[4];
                uint32_t addr = kbase + ((kg * 16 + (lane & 7) + ((lane >> 4) << 3)) * KSTR2
                                         + (kc & 3) * 16 + (((lane >> 3) & 1) << 3)) * 2;
                ldm_x4(b, addr);
                mma16816(sc[kg * 2],     qf[kc], b);
                mma16816(sc[kg * 2 + 1], qf[kc], b + 2);
            }
        }

        // online softmax (log2 domain; Q pre-scaled by log2e/8)
        float m0 = -1e30f, m1 = -1e30f;
        #pragma unroll
        for (int t = 0; t < 16; t++) {
            m0 = fmaxf(m0, fmaxf(sc[t][0], sc[t][1]));
            m1 = fmaxf(m1, fmaxf(sc[t][2], sc[t][3]));
        }
        #pragma unroll
        for (int off = 1; off <= 2; off <<= 1) {
            m0 = fmaxf(m0, __shfl_xor_sync(0xffffffffu, m0, off));
            m1 = fmaxf(m1, __shfl_xor_sync(0xffffffffu, m1, off));
        }
        float nM0 = fmaxf(M0, m0), nM1 = fmaxf(M1, m1);
        float a0 = ex2f(M0 - nM0), a1 = ex2f(M1 - nM1);
        M0 = nM0; M1 = nM1;
        float s0 = 0.f, s1 = 0.f;
        #pragma unroll
        for (int t = 0; t < 16; t++) {
            sc[t][0] = ex2f(sc[t][0] - M0); s0 += sc[t][0];
            sc[t][1] = ex2f(sc[t][1] - M0); s0 += sc[t][1];
            sc[t][2] = ex2f(sc[t][2] - M1); s1 += sc[t][2];
            sc[t][3] = ex2f(sc[t][3] - M1); s1 += sc[t][3];
        }
        #pragma unroll
        for (int off = 1; off <= 2; off <<= 1) {
            s0 += __shfl_xor_sync(0xffffffffu, s0, off);
            s1 += __shfl_xor_sync(0xffffffffu, s1, off);
        }
        L0 = L0 * a0 + s0; L1 = L1 * a1 + s1;
        #pragma unroll
        for (int j = 0; j < 8; j++) {
            oacc[j][0] *= a0; oacc[j][1] *= a0;
            oacc[j][2] *= a1; oacc[j][3] *= a1;
        }

        // PV: 2 chains  ((Phi + Plo) * Vhi)
        #pragma unroll
        for (int j = 0; j < 8; j++) {
            uint32_t ph[4], pl[4];
            float c00 = sc[2*j][0],   c01 = sc[2*j][1];
            float c02 = sc[2*j][2],   c03 = sc[2*j][3];
            float c10 = sc[2*j+1][0], c11 = sc[2*j+1][1];
            float c12 = sc[2*j+1][2], c13 = sc[2*j+1][3];
            ph[0] = pkh2(c00, c01); ph[1] = pkh2(c02, c03);
            ph[2] = pkh2(c10, c11); ph[3] = pkh2(c12, c13);
            float h00, h01, h02, h03, h10, h11, h12, h13;
            unpkh2(ph[0], h00, h01); unpkh2(ph[1], h02, h03);
            unpkh2(ph[2], h10, h11); unpkh2(ph[3], h12, h13);
            pl[0] = pkh2(c00 - h00, c01 - h01); pl[1] = pkh2(c02 - h02, c03 - h03);
            pl[2] = pkh2(c10 - h10, c11 - h11); pl[3] = pkh2(c12 - h12, c13 - h13);

            uint32_t koff = (j * 16 + (((lane >> 3) & 1) << 3)) * 2;
            uint32_t rsel = (lane & 7) + ((lane >> 4) << 3);
            #pragma unroll
            for (int dg = 0; dg < 4; dg++) {
                uint32_t row = dg * 16 + rsel;
                uint32_t bh4[4];
                ldm_x4(bh4, vbase + row * (VSTR * 2) + koff);
                mma16816(oacc[dg * 2],     ph, bh4);
                mma16816(oacc[dg * 2 + 1], ph, bh4 + 2);
                mma16816(oacc[dg * 2],     pl, bh4);
                mma16816(oacc[dg * 2 + 1], pl, bh4 + 2);
            }
        }
    }

    // epilogue: normalize + packed ctx write [hi | lo]
    float i0 = 1.f / L0, i1 = 1.f / L1;
    int r = lane >> 2;
    int q0 = qt * 64 + wid * 16;
    size_t row0 = ((size_t)(b_ * SS + q0 + r)) * KP2;
    size_t row1 = ((size_t)(b_ * SS + q0 + r + 8)) * KP2;
    int cbase = h_ * DH + (lane & 3) * 2;
    #pragma unroll
    for (int t = 0; t < 8; t++) {
        int col = cbase + t * 8;
        float v0 = oacc[t][0] * i0, v1 = oacc[t][1] * i0;
        float w0 = oacc[t][2] * i1, w1 = oacc[t][3] * i1;
        uint32_t pv = pkh2(v0, v1);
        uint32_t pw = pkh2(w0, w1);
        float vh0, vh1, wh0, wh1;
        unpkh2(pv, vh0, vh1); unpkh2(pw, wh0, wh1);
        *(uint32_t*)&Ctx[row0 + col]        = pv;
        *(uint32_t*)&Ctx[row0 + 1024 + col] = pkh2(v0 - vh0, v1 - vh1);
        *(uint32_t*)&Ctx[row1 + col]        = pw;
        *(uint32_t*)&Ctx[row1 + 1024 + col] = pkh2(w0 - wh0, w1 - wh1);
    }
}

// ------------------------- launch -------------------------
extern "C" void kernel_launch(void* const* d_in, const int* in_sizes, int n_in,
                              void* d_out, int out_size)
{
    const float* key   = (const float*)d_in[0];
    const float* value = (const float*)d_in[1];
    const float* query = (const float*)d_in[2];
    const float* wq = (const float*)d_in[3];
    const float* bq = (const float*)d_in[4];
    const float* wk = (const float*)d_in[5];
    const float* bk = (const float*)d_in[6];
    const float* wv = (const float*)d_in[7];
    const float* bv = (const float*)d_in[8];
    const float* wo = (const float*)d_in[9];
    const float* bo = (const float*)d_in[10];
    float* out = (float*)d_out;

    __half *xp, *wt, *qp, *kp, *vt;
    cudaGetSymbolAddress((void**)&xp, g_Xp);
    cudaGetSymbolAddress((void**)&wt, g_Wt);
    cudaGetSymbolAddress((void**)&qp, g_Qp);
    cudaGetSymbolAddress((void**)&kp, g_Kp);
    cudaGetSymbolAddress((void**)&vt, g_Vt);

    constexpr int SMG  = 2 * GSTAGE > 128 * STG_STR * 4 ? 2 * GSTAGE : 128 * STG_STR * 4; // 147456
    constexpr int SMFL = 2 * KBUF2 + 2 * VBUF2;       // 71680
    cudaFuncSetAttribute(gemm_u,  cudaFuncAttributeMaxDynamicSharedMemorySize, SMG);
    cudaFuncSetAttribute(flash_k, cudaFuncAttributeMaxDynamicSharedMemorySize, SMFL);

    pack_wt_k<<<dim3(32, 32, 4), 256>>>(wq, wk, wv, wo, wt);
    pack_a_k<<<dim3(MTOT * HH / 1024, 3), 256>>>(query, key, value, xp);

    // merged QKV projections (z: 0=Q,1=K,2=Vt), CTA 128x256
    gemm_u<<<dim3(4, 64, 3), 256, SMG>>>(xp, wt, nullptr, qp, kp, vt,
                                         bq, bk, bv, -1);

    // fused attention -> packed ctx in Xp slab 0 (64 q-rows per CTA, 2 CTAs/SM)
    flash_k<<<dim3(32, 64), 128, SMFL>>>(qp, kp, vt, xp);

    // output projection
    gemm_u<<<dim3(4, 64, 1), 256, SMG>>>(xp, wt + 3 * WSLAB, out,
                                         nullptr, nullptr, nullptr,
                                         bo, bo, bo, 3);
}

// round 17
// speedup vs baseline: 1.5908x; 1.1066x over previous
#include <cuda_runtime.h>
#include <cuda_fp16.h>
#include <cstdint>

#define BB 4
#define SS 2048
#define NHD 16
#define DH 64
#define HH 1024
#define MTOT (BB*SS)     // 8192
#define KP2 2048         // packed A-side K ([hi|lo])
#define WKP 1024         // packed B-side (hi only, reused)
#define KQ 128           // packed Q k-dim [hi|lo]
#define LOG2E 1.4426950408889634f

#define ASLAB ((size_t)MTOT*KP2)
#define WSLAB ((size_t)HH*WKP)

// ------------------------- scratch (device globals) -------------------------
__device__ __half g_Xp[3*ASLAB];                 // packed acts (q,k,v); ctx in slab0
__device__ __half g_Wt[4*WSLAB];                 // W^T hi (fp16)
__device__ __half g_Qp[(size_t)BB*NHD*SS*KQ];    // [qhi|qlo]
__device__ __half g_Kp[(size_t)BB*NHD*SS*DH];    // k hi only
__device__ __half g_Vt[(size_t)BB*NHD*DH*SS];    // v^T hi only

// ------------------------- helpers -------------------------
__device__ __forceinline__ uint32_t s2u(const void* p) {
    uint32_t a;
    asm("{ .reg .u64 t; cvta.to.shared.u64 t, %1; cvt.u32.u64 %0, t; }" : "=r"(a) : "l"(p));
    return a;
}
#define CP_ASYNC16(dst, src) \
    asm volatile("cp.async.cg.shared.global [%0], [%1], 16;" :: "r"(dst), "l"(src))
#define CP_COMMIT() asm volatile("cp.async.commit_group;" ::: "memory")
#define CP_WAIT(n)  asm volatile("cp.async.wait_group %0;" :: "n"(n) : "memory")

__device__ __forceinline__ void ldm_x4(uint32_t* r, uint32_t addr) {
    asm volatile("ldmatrix.sync.aligned.m8n8.x4.shared.b16 {%0,%1,%2,%3}, [%4];"
        : "=r"(r[0]), "=r"(r[1]), "=r"(r[2]), "=r"(r[3]) : "r"(addr));
}
__device__ __forceinline__ void mma16816(float* d, const uint32_t* a, const uint32_t* b) {
    asm volatile("mma.sync.aligned.m16n8k16.row.col.f32.f16.f16.f32 "
        "{%0,%1,%2,%3}, {%4,%5,%6,%7}, {%8,%9}, {%0,%1,%2,%3};"
        : "+f"(d[0]), "+f"(d[1]), "+f"(d[2]), "+f"(d[3])
        : "r"(a[0]), "r"(a[1]), "r"(a[2]), "r"(a[3]), "r"(b[0]), "r"(b[1]));
}
__device__ __forceinline__ uint32_t pkh2(float lo, float hi) {   // low half = lo
    uint32_t r;
    asm("cvt.rn.f16x2.f32 %0, %1, %2;" : "=r"(r) : "f"(hi), "f"(lo));
    return r;
}
__device__ __forceinline__ void unpkh2(uint32_t p, float& lo, float& hi) {
    __half2 h = *(__half2*)&p;
    lo = __low2float(h); hi = __high2float(h);
}
__device__ __forceinline__ float ex2f(float x) {
    float r;
    asm("ex2.approx.ftz.f32 %0, %1;" : "=f"(r) : "f"(x));
    return r;
}

// ------------------------- pack kernels -------------------------
__global__ __launch_bounds__(256) void pack_a_k(
    const float* __restrict__ q, const float* __restrict__ k,
    const float* __restrict__ v, __half* __restrict__ xpBase)
{
    int z = blockIdx.y;
    const float* x = (z == 0) ? q : (z == 1) ? k : v;
    __half* xp = xpBase + (size_t)z * ASLAB;
    int i = blockIdx.x * 256 + threadIdx.x;
    int row = i >> 8;
    int k4 = (i & 255) << 2;
    float4 f = *(const float4*)&x[((size_t)row << 10) + k4];
    uint32_t p01 = pkh2(f.x, f.y), p23 = pkh2(f.z, f.w);
    float h0, h1, h2, h3;
    unpkh2(p01, h0, h1); unpkh2(p23, h2, h3);
    uint32_t l01 = pkh2(f.x - h0, f.y - h1), l23 = pkh2(f.z - h2, f.w - h3);
    size_t base = (size_t)row * KP2 + k4;
    *(uint32_t*)&xp[base]          = p01;
    *(uint32_t*)&xp[base + 2]      = p23;
    *(uint32_t*)&xp[base + 1024]   = l01;
    *(uint32_t*)&xp[base + 1026]   = l23;
}

__global__ __launch_bounds__(256) void pack_wt_k(
    const float* __restrict__ wq, const float* __restrict__ wk,
    const float* __restrict__ wv, const float* __restrict__ wo,
    __half* __restrict__ wtBase)
{
    __shared__ float t[32][33];
    int z = blockIdx.z;
    const float* W = (z == 0) ? wq : (z == 1) ? wk : (z == 2) ? wv : wo;
    __half* Wt = wtBase + (size_t)z * WSLAB;
    int tx = threadIdx.x & 31, ty = threadIdx.x >> 5;
    int n0 = blockIdx.x * 32, k0 = blockIdx.y * 32;
    #pragma unroll
    for (int r = 0; r < 4; r++) {
        int k = k0 + ty + r * 8;
        t[ty + r * 8][tx] = W[(size_t)k * HH + n0 + tx];
    }
    __syncthreads();
    #pragma unroll
    for (int r = 0; r < 4; r++) {
        int n = n0 + ty + r * 8;
        int k = k0 + tx;
        Wt[(size_t)n * WKP + k] = __float2half(t[tx][ty + r * 8]);
    }
}

// ------------------------- universal GEMM: lo-chain only where output precision needs it -------------------------
#define LDS2 72
#define BUFA (128*LDS2*2)    // 18432
#define BUFB (256*LDS2*2)    // 36864
#define GSTAGE (2*BUFA+BUFB) // 73728
#define STG_STR 258

__global__ __launch_bounds__(256) void gemm_u(
    const __half* __restrict__ Abase, const __half* __restrict__ Wbase,
    float* __restrict__ outf, __half* __restrict__ outq,
    __half* __restrict__ outk, __half* __restrict__ outvt,
    const float* __restrict__ b0, const float* __restrict__ b1,
    const float* __restrict__ b2, int fixedMode)
{
    extern __shared__ char smem[];
    const int tid = threadIdx.x, wid = tid >> 5, lane = tid & 31;
    const int m0 = blockIdx.y * 128, n0 = blockIdx.x * 256;
    const int z = blockIdx.z;
    const int epi = (fixedMode < 0) ? z : fixedMode;
    // K (epi 1) and VT (epi 2) outputs are rounded to fp16 anyway: skip lo chain
    const bool useLo = (epi == 0 || epi == 3);

    const uint32_t sb = s2u(smem);

    const __half* Ab = Abase + ((fixedMode < 0) ? (size_t)z * ASLAB : 0) + (size_t)m0 * KP2;
    const __half* Bb = Wbase + ((fixedMode < 0) ? (size_t)z * WSLAB : 0) + (size_t)n0 * WKP;
    const float* bias = (epi == 0) ? b0 : (epi == 1) ? b1 : (epi == 2) ? b2 : b0;
    const float scale = (epi == 0) ? (0.125f * LOG2E) : 1.0f;
    constexpr int nC = 16;

    auto loadChunk = [&](int c, int s) {
        const uint32_t uAhi = sb + s * GSTAGE;
        const uint32_t uAlo = uAhi + BUFA;
        const uint32_t uB   = uAhi + 2 * BUFA;
        const __half* ahp = Ab + c * 64;
        const __half* alp = Ab + 1024 + c * 64;
        const __half* bp  = Bb + c * 64;
        #pragma unroll
        for (int p = 0; p < 4; p++) {
            int idx = tid + p * 256;
            int r = idx >> 3, sg = idx & 7;
            CP_ASYNC16(uAhi + r * (LDS2 * 2) + sg * 16,
                       (const char*)(ahp + (size_t)r * KP2) + sg * 16);
        }
        if (useLo) {
            #pragma unroll
            for (int p = 0; p < 4; p++) {
                int idx = tid + p * 256;
                int r = idx >> 3, sg = idx & 7;
                CP_ASYNC16(uAlo + r * (LDS2 * 2) + sg * 16,
                           (const char*)(alp + (size_t)r * KP2) + sg * 16);
            }
        }
        #pragma unroll
        for (int p = 0; p < 8; p++) {
            int idx = tid + p * 256;
            int r = idx >> 3, sg = idx & 7;
            CP_ASYNC16(uB + r * (LDS2 * 2) + sg * 16,
                       (const char*)(bp + (size_t)r * WKP) + sg * 16);
        }
        CP_COMMIT();
    };

    float acc[4][8][4];
    #pragma unroll
    for (int i = 0; i < 4; i++)
        #pragma unroll
        for (int j = 0; j < 8; j++)
            #pragma unroll
            for (int q = 0; q < 4; q++) acc[i][j][q] = 0.f;

    const int wm = (wid & 1) * 64;
    const int wn = (wid >> 1) * 64;

    loadChunk(0, 0);
    for (int c = 0; c < nC; c++) {
        int buf = c & 1;
        if (c + 1 < nC) { loadChunk(c + 1, (c + 1) & 1); CP_WAIT(1); }
        else CP_WAIT(0);
        __syncthreads();
        const uint32_t uAhi = sb + buf * GSTAGE;
        const uint32_t uAlo = uAhi + BUFA;
        const uint32_t uB   = uAhi + 2 * BUFA;
        #pragma unroll
        for (int ks = 0; ks < 4; ks++) {
            uint32_t ah[4][4], al[4][4];
            #pragma unroll
            for (int im = 0; im < 4; im++) {
                uint32_t off = ((wm + im * 16 + (lane & 15)) * LDS2
                                + ks * 16 + (lane >> 4) * 8) * 2;
                ldm_x4(ah[im], uAhi + off);
                if (useLo) ldm_x4(al[im], uAlo + off);
            }
            uint32_t b[4][4];
            #pragma unroll
            for (int ig = 0; ig < 4; ig++) {
                uint32_t addr = uB +
                    ((wn + ig * 16 + (lane & 7) + ((lane >> 4) << 3)) * LDS2
                     + ks * 16 + (((lane >> 3) & 1) << 3)) * 2;
                ldm_x4(b[ig], addr);
            }
            #pragma unroll
            for (int im = 0; im < 4; im++)
                #pragma unroll
                for (int ig = 0; ig < 4; ig++) {
                    mma16816(acc[im][ig * 2],     ah[im], &b[ig][0]);
                    mma16816(acc[im][ig * 2 + 1], ah[im], &b[ig][2]);
                }
            if (useLo) {
                #pragma unroll
                for (int im = 0; im < 4; im++)
                    #pragma unroll
                    for (int ig = 0; ig < 4; ig++) {
                        mma16816(acc[im][ig * 2],     al[im], &b[ig][0]);
                        mma16816(acc[im][ig * 2 + 1], al[im], &b[ig][2]);
                    }
            }
        }
        __syncthreads();
    }

    // ------------------- epilogues -------------------
    if (epi == 2) {
        float* stage = (float*)smem;
        #pragma unroll
        for (int im = 0; im < 4; im++)
            #pragma unroll
            for (int jn = 0; jn < 8; jn++)
                #pragma unroll
                for (int h2 = 0; h2 < 2; h2++)
                    #pragma unroll
                    for (int cc = 0; cc < 2; cc++) {
                        int ml = wm + im * 16 + (lane >> 2) + h2 * 8;
                        int nl = wn + jn * 8 + (lane & 3) * 2 + cc;
                        stage[ml * STG_STR + nl] = acc[im][jn][h2 * 2 + cc] + bias[n0 + nl];
                    }
        __syncthreads();
        {
            const int bI = m0 >> 11, sBase = m0 & (SS - 1);
            int gl = tid;
            int gn = n0 + gl;
            int h = gn >> 6, d = gn & 63;
            size_t base = ((size_t)((bI * NHD + h) * DH + d)) * SS;
            #pragma unroll 4
            for (int sl = 0; sl < 128; sl++)
                outvt[base + sBase + sl] = __float2half(stage[sl * STG_STR + gl]);
        }
    } else if (epi == 3) {
        #pragma unroll
        for (int im = 0; im < 4; im++)
            #pragma unroll
            for (int jn = 0; jn < 8; jn++)
                #pragma unroll
                for (int h2 = 0; h2 < 2; h2++) {
                    int m = m0 + wm + im * 16 + (lane >> 2) + h2 * 8;
                    int gn = n0 + wn + jn * 8 + (lane & 3) * 2;
                    float2 r2;
                    r2.x = acc[im][jn][h2 * 2]     + bias[gn];
                    r2.y = acc[im][jn][h2 * 2 + 1] + bias[gn + 1];
                    *(float2*)&outf[(size_t)m * HH + gn] = r2;
                }
    } else {
        #pragma unroll
        for (int im = 0; im < 4; im++)
            #pragma unroll
            for (int jn = 0; jn < 8; jn++)
                #pragma unroll
                for (int h2 = 0; h2 < 2; h2++) {
                    int m = m0 + wm + im * 16 + (lane >> 2) + h2 * 8;
                    int gn = n0 + wn + jn * 8 + (lane & 3) * 2;
                    float v0 = (acc[im][jn][h2 * 2]     + bias[gn])     * scale;
                    float v1 = (acc[im][jn][h2 * 2 + 1] + bias[gn + 1]) * scale;
                    int h = gn >> 6, d = gn & 63;
                    int bI = m >> 11, sI = m & (SS - 1);
                    uint32_t phi = pkh2(v0, v1);
                    if (epi == 0) {  // Q: [hi | lo]
                        float fh0, fh1; unpkh2(phi, fh0, fh1);
                        uint32_t plo = pkh2(v0 - fh0, v1 - fh1);
                        size_t base = ((size_t)(bI * NHD + h) * SS + sI) * KQ;
                        *(uint32_t*)&outq[base + d]      = phi;
                        *(uint32_t*)&outq[base + 64 + d] = plo;
                    } else {         // K: hi only
                        size_t base = ((size_t)(bI * NHD + h) * SS + sI) * DH;
                        *(uint32_t*)&outk[base + d] = phi;
                    }
                }
    }
}

// ------------------------- fused flash attention (R16 verbatim: 128 thr, 2 CTAs/SM) -------------------------
#define QSTR 136
#define KSTR2 72
#define KBUF2 (128*KSTR2*2)   // 18432
#define VSTR 136
#define VBUF2 (64*VSTR*2)     // 17408

__global__ __launch_bounds__(128, 2) void flash_k(
    const __half* __restrict__ Qp, const __half* __restrict__ Kp,
    const __half* __restrict__ Vt, __half* __restrict__ Ctx)
{
    extern __shared__ char smem[];
    const int tid = threadIdx.x, wid = tid >> 5, lane = tid & 31;
    const int qt = blockIdx.x, bh = blockIdx.y;
    const int b_ = bh >> 4, h_ = bh & 15;
    const uint32_t sb = s2u(smem);
    const uint32_t uKb[2] = { sb, sb + KBUF2 };
    const uint32_t uVb[2] = { sb + 2 * KBUF2, sb + 2 * KBUF2 + VBUF2 };

    const __half* Qb = Qp + ((size_t)bh * SS + qt * 64) * KQ;
    const __half* Kb = Kp + (size_t)bh * SS * DH;
    const __half* Vb = Vt + (size_t)bh * DH * SS;

    auto issueK = [&](int it) {
        const __half* kp2 = Kb + (size_t)(it * 128) * DH;
        uint32_t dst = uKb[it & 1];
        #pragma unroll
        for (int p = 0; p < 8; p++) {
            int idx = tid + p * 128;
            int r = idx >> 3, sg = idx & 7;
            CP_ASYNC16(dst + r * (KSTR2 * 2) + sg * 16,
                       (const char*)(kp2 + (size_t)r * DH) + sg * 16);
        }
        CP_COMMIT();
    };
    auto issueV = [&](int it) {
        uint32_t dst = uVb[it & 1];
        int kt = it * 128;
        #pragma unroll
        for (int p = 0; p < 8; p++) {
            int idx = tid + p * 128;
            int r = idx >> 4, sg = idx & 15;
            CP_ASYNC16(dst + r * (VSTR * 2) + sg * 16,
                       (const char*)(Vb + (size_t)r * SS + kt) + sg * 16);
        }
        CP_COMMIT();
    };

    // prologue: stage Q (64 rows x 128 halfs) into K-buffer region
    #pragma unroll
    for (int p = 0; p < 8; p++) {
        int idx = tid + p * 128;
        int r = idx >> 4, sg = idx & 15;
        CP_ASYNC16(sb + r * (QSTR * 2) + sg * 16,
                   (const char*)(Qb + (size_t)r * KQ) + sg * 16);
    }
    CP_COMMIT();
    CP_WAIT(0); __syncthreads();

    uint32_t qf[8][4];
    {
        int rbase = wid * 16 + (lane & 15);
        #pragma unroll
        for (int kc = 0; kc < 8; kc++)
            ldm_x4(qf[kc], sb + (rbase * QSTR + kc * 16 + (lane >> 4) * 8) * 2);
    }
    __syncthreads();

    issueK(0); issueV(0);

    float oacc[8][4];
    #pragma unroll
    for (int j = 0; j < 8; j++)
        #pragma unroll
        for (int q = 0; q < 4; q++) oacc[j][q] = 0.f;
    float M0 = -1e30f, M1 = -1e30f, L0 = 0.f, L1 = 0.f;

    for (int i = 0; i < 16; i++) {
        CP_WAIT(0);
        __syncthreads();
        if (i + 1 < 16) { issueK(i + 1); issueV(i + 1); }

        const uint32_t kbase = uKb[i & 1];
        const uint32_t vbase = uVb[i & 1];

        float sc[16][4];
        #pragma unroll
        for (int t = 0; t < 16; t++)
            #pragma unroll
            for (int q = 0; q < 4; q++) sc[t][q] = 0.f;
        #pragma unroll
        for (int kc = 0; kc < 8; kc++) {
            #pragma unroll
            for (int kg = 0; kg < 8; kg++) {
                uint32_t b[4];
                uint32_t addr = kbase + ((kg * 16 + (lane & 7) + ((lane >> 4) << 3)) * KSTR2
                                         + (kc & 3) * 16 + (((lane >> 3) & 1) << 3)) * 2;
                ldm_x4(b, addr);
                mma16816(sc[kg * 2],     qf[kc], b);
                mma16816(sc[kg * 2 + 1], qf[kc], b + 2);
            }
        }

        float m0 = -1e30f, m1 = -1e30f;
        #pragma unroll
        for (int t = 0; t < 16; t++) {
            m0 = fmaxf(m0, fmaxf(sc[t][0], sc[t][1]));
            m1 = fmaxf(m1, fmaxf(sc[t][2], sc[t][3]));
        }
        #pragma unroll
        for (int off = 1; off <= 2; off <<= 1) {
            m0 = fmaxf(m0, __shfl_xor_sync(0xffffffffu, m0, off));
            m1 = fmaxf(m1, __shfl_xor_sync(0xffffffffu, m1, off));
        }
        float nM0 = fmaxf(M0, m0), nM1 = fmaxf(M1, m1);
        float a0 = ex2f(M0 - nM0), a1 = ex2f(M1 - nM1);
        M0 = nM0; M1 = nM1;
        float s0 = 0.f, s1 = 0.f;
        #pragma unroll
        for (int t = 0; t < 16; t++) {
            sc[t][0] = ex2f(sc[t][0] - M0); s0 += sc[t][0];
            sc[t][1] = ex2f(sc[t][1] - M0); s0 += sc[t][1];
            sc[t][2] = ex2f(sc[t][2] - M1); s1 += sc[t][2];
            sc[t][3] = ex2f(sc[t][3] - M1); s1 += sc[t][3];
        }
        #pragma unroll
        for (int off = 1; off <= 2; off <<= 1) {
            s0 += __shfl_xor_sync(0xffffffffu, s0, off);
            s1 += __shfl_xor_sync(0xffffffffu, s1, off);
        }
        L0 = L0 * a0 + s0; L1 = L1 * a1 + s1;
        #pragma unroll
        for (int j = 0; j < 8; j++) {
            oacc[j][0] *= a0; oacc[j][1] *= a0;
            oacc[j][2] *= a1; oacc[j][3] *= a1;
        }

        // PV: 2 chains  ((Phi + Plo) * Vhi)
        #pragma unroll
        for (int j = 0; j < 8; j++) {
            uint32_t ph[4], pl[4];
            float c00 = sc[2*j][0],   c01 = sc[2*j][1];
            float c02 = sc[2*j][2],   c03 = sc[2*j][3];
            float c10 = sc[2*j+1][0], c11 = sc[2*j+1][1];
            float c12 = sc[2*j+1][2], c13 = sc[2*j+1][3];
            ph[0] = pkh2(c00, c01); ph[1] = pkh2(c02, c03);
            ph[2] = pkh2(c10, c11); ph[3] = pkh2(c12, c13);
            float h00, h01, h02, h03, h10, h11, h12, h13;
            unpkh2(ph[0], h00, h01); unpkh2(ph[1], h02, h03);
            unpkh2(ph[2], h10, h11); unpkh2(ph[3], h12, h13);
            pl[0] = pkh2(c00 - h00, c01 - h01); pl[1] = pkh2(c02 - h02, c03 - h03);
            pl[2] = pkh2(c10 - h10, c11 - h11); pl[3] = pkh2(c12 - h12, c13 - h13);

            uint32_t koff = (j * 16 + (((lane >> 3) & 1) << 3)) * 2;
            uint32_t rsel = (lane & 7) + ((lane >> 4) << 3);
            #pragma unroll
            for (int dg = 0; dg < 4; dg++) {
                uint32_t row = dg * 16 + rsel;
                uint32_t bh4[4];
                ldm_x4(bh4, vbase + row * (VSTR * 2) + koff);
                mma16816(oacc[dg * 2],     ph, bh4);
                mma16816(oacc[dg * 2 + 1], ph, bh4 + 2);
                mma16816(oacc[dg * 2],     pl, bh4);
                mma16816(oacc[dg * 2 + 1], pl, bh4 + 2);
            }
        }
    }

    // epilogue: normalize + packed ctx write [hi | lo]
    float i0 = 1.f / L0, i1 = 1.f / L1;
    int r = lane >> 2;
    int q0 = qt * 64 + wid * 16;
    size_t row0 = ((size_t)(b_ * SS + q0 + r)) * KP2;
    size_t row1 = ((size_t)(b_ * SS + q0 + r + 8)) * KP2;
    int cbase = h_ * DH + (lane & 3) * 2;
    #pragma unroll
    for (int t = 0; t < 8; t++) {
        int col = cbase + t * 8;
        float v0 = oacc[t][0] * i0, v1 = oacc[t][1] * i0;
        float w0 = oacc[t][2] * i1, w1 = oacc[t][3] * i1;
        uint32_t pv = pkh2(v0, v1);
        uint32_t pw = pkh2(w0, w1);
        float vh0, vh1, wh0, wh1;
        unpkh2(pv, vh0, vh1); unpkh2(pw, wh0, wh1);
        *(uint32_t*)&Ctx[row0 + col]        = pv;
        *(uint32_t*)&Ctx[row0 + 1024 + col] = pkh2(v0 - vh0, v1 - vh1);
        *(uint32_t*)&Ctx[row1 + col]        = pw;
        *(uint32_t*)&Ctx[row1 + 1024 + col] = pkh2(w0 - wh0, w1 - wh1);
    }
}

// ------------------------- launch -------------------------
extern "C" void kernel_launch(void* const* d_in, const int* in_sizes, int n_in,
                              void* d_out, int out_size)
{
    const float* key   = (const float*)d_in[0];
    const float* value = (const float*)d_in[1];
    const float* query = (const float*)d_in[2];
    const float* wq = (const float*)d_in[3];
    const float* bq = (const float*)d_in[4];
    const float* wk = (const float*)d_in[5];
    const float* bk = (const float*)d_in[6];
    const float* wv = (const float*)d_in[7];
    const float* bv = (const float*)d_in[8];
    const float* wo = (const float*)d_in[9];
    const float* bo = (const float*)d_in[10];
    float* out = (float*)d_out;

    __half *xp, *wt, *qp, *kp, *vt;
    cudaGetSymbolAddress((void**)&xp, g_Xp);
    cudaGetSymbolAddress((void**)&wt, g_Wt);
    cudaGetSymbolAddress((void**)&qp, g_Qp);
    cudaGetSymbolAddress((void**)&kp, g_Kp);
    cudaGetSymbolAddress((void**)&vt, g_Vt);

    constexpr int SMG  = 2 * GSTAGE > 128 * STG_STR * 4 ? 2 * GSTAGE : 128 * STG_STR * 4; // 147456
    constexpr int SMFL = 2 * KBUF2 + 2 * VBUF2;       // 71680
    cudaFuncSetAttribute(gemm_u,  cudaFuncAttributeMaxDynamicSharedMemorySize, SMG);
    cudaFuncSetAttribute(flash_k, cudaFuncAttributeMaxDynamicSharedMemorySize, SMFL);

    pack_wt_k<<<dim3(32, 32, 4), 256>>>(wq, wk, wv, wo, wt);
    pack_a_k<<<dim3(MTOT * HH / 1024, 3), 256>>>(query, key, value, xp);

    // merged QKV projections (z: 0=Q,1=K,2=Vt), CTA 128x256
    gemm_u<<<dim3(4, 64, 3), 256, SMG>>>(xp, wt, nullptr, qp, kp, vt,
                                         bq, bk, bv, -1);

    // fused attention -> packed ctx in Xp slab 0 (64 q-rows per CTA, 2 CTAs/SM)
    flash_k<<<dim3(32, 64), 128, SMFL>>>(qp, kp, vt, xp);

    // output projection
    gemm_u<<<dim3(4, 64, 1), 256, SMG>>>(xp, wt + 3 * WSLAB, out,
                                         nullptr, nullptr, nullptr,
                                         bo, bo, bo, 3);
}